// round 5
// baseline (speedup 1.0000x reference)
#include <cuda_runtime.h>

// Problem constants
#define Hn    128
#define Ln    512
#define Bn    128
#define NPTn  1023                 // 2L-1 nodes per tree
#define NTOT  (Bn * NPTn)          // 130944 nodes
#define NLEAF (Bn * Ln)            // 65536 leaves

// Persistent device state (no allocation allowed)
__device__ float g_h[NTOT * Hn];                 // 67 MB
__device__ float g_c[NTOT * Hn];                 // 67 MB
__device__ float g_scratch[NLEAF * 384];         // 100.7 MB; levels use stride 640

__device__ __forceinline__ float sigm(float x) { return 1.0f / (1.0f + expf(-x)); }

// Packed fp32x2 FMA (Blackwell FFMA2) — only reachable via explicit PTX.
#define FMA_F32X2(d, a, b, c) \
    asm("fma.rn.f32x2 %0, %1, %2, %3;" : "=l"(d) : "l"(a), "l"(b), "l"(c))

// ---------------------------------------------------------------------------
// f32x2 tiled GEMM. Thread layout 16x16, micro-tile MT rows x 8 cols.
// BM = MT*16, BN = 128, BK = 32.
// A tile stored in smem pre-duplicated as float2{a,a} so LDS.64 gives a
// broadcast-packed operand — the inner loop is pure FFMA2.
// ---------------------------------------------------------------------------
#define BNf 128
#define BKf 32

// ======================= Leaf GEMM =======================
// scratch[r, 0:384] = emb[label[leaf_node(r)]] @ W_iou   (K = 128)
// grid (NLEAF/64, 3), block 256
__global__ __launch_bounds__(256) void leaf_gemm_f2(const int* __restrict__ label,
                                                    const float* __restrict__ emb,
                                                    const float* __restrict__ W) {
    const int MT = 4, BM = 64;
    __shared__ float2 As2[BM * BKf];      // duplicated A: 16 KB
    __shared__ float  Bs[BKf * BNf];      // 16 KB
    __shared__ int abase[BM];

    int tid  = threadIdx.x;
    int row0 = blockIdx.x * BM;
    int col0 = blockIdx.y * BNf;

    if (tid < BM) {
        int r = row0 + tid;
        int g = (r >> 9) * NPTn + (r & 511);
        abase[tid] = label[g] * Hn;
    }
    __syncthreads();

    int ty = tid >> 4, tx = tid & 15;
    unsigned long long acc[MT][4];
#pragma unroll
    for (int i = 0; i < MT; i++)
#pragma unroll
        for (int p = 0; p < 4; p++) acc[i][p] = 0ull;

    for (int kk = 0; kk < Hn; kk += BKf) {
        // Stage A (duplicated)
#pragma unroll
        for (int e = tid; e < BM * (BKf / 4); e += 256) {
            int m  = e >> 3;
            int kq = (e & 7) * 4;
            float4 v = *(const float4*)(emb + abase[m] + kk + kq);
            float2* dst = As2 + m * BKf + kq;
            *(float4*)(dst)     = make_float4(v.x, v.x, v.y, v.y);
            *(float4*)(dst + 2) = make_float4(v.z, v.z, v.w, v.w);
        }
        // Stage B
#pragma unroll
        for (int e = tid; e < BKf * (BNf / 4); e += 256) {
            int k = e >> 5;
            int c = (e & 31) * 4;
            *(float4*)(Bs + k * BNf + c) = *(const float4*)(W + (kk + k) * 384 + col0 + c);
        }
        __syncthreads();

        const unsigned long long* Au = (const unsigned long long*)As2;
#pragma unroll
        for (int k = 0; k < BKf; k++) {
            ulonglong2 b0 = *(const ulonglong2*)(Bs + k * BNf + tx * 8);
            ulonglong2 b1 = *(const ulonglong2*)(Bs + k * BNf + tx * 8 + 4);
#pragma unroll
            for (int i = 0; i < MT; i++) {
                unsigned long long a = Au[(ty * MT + i) * BKf + k];
                FMA_F32X2(acc[i][0], a, b0.x, acc[i][0]);
                FMA_F32X2(acc[i][1], a, b0.y, acc[i][1]);
                FMA_F32X2(acc[i][2], a, b1.x, acc[i][2]);
                FMA_F32X2(acc[i][3], a, b1.y, acc[i][3]);
            }
        }
        __syncthreads();
    }
#pragma unroll
    for (int i = 0; i < MT; i++) {
        int r = row0 + ty * MT + i;
        float* drow = g_scratch + (size_t)r * 384 + col0 + tx * 8;
        union { unsigned long long u[2]; float4 f; } cv;
        cv.u[0] = acc[i][0]; cv.u[1] = acc[i][1];
        *(float4*)(drow) = cv.f;
        cv.u[0] = acc[i][2]; cv.u[1] = acc[i][3];
        *(float4*)(drow + 4) = cv.f;
    }
}

// ======================= Level GEMM =======================
// scratch[r, 0:256] = h_cat @ U_f_w ; scratch[r, 256:640] = h_cat @ U_iou
// h_cat row = 256 contiguous floats at g_h + left*Hn (right node = left+1).
// grid (nd/BM, 5), block 256.
template <int MT>
__global__ __launch_bounds__(256) void level_gemm_f2(const float* __restrict__ Ufw,
                                                     const float* __restrict__ Uiou,
                                                     int shift, int choff) {
    const int BM = MT * 16;
    __shared__ float2 As2[BM * BKf];
    __shared__ float  Bs[BKf * BNf];
    __shared__ int lbase[BM];

    int tid  = threadIdx.x;
    int row0 = blockIdx.x * BM;
    int col0 = blockIdx.y * BNf;

    if (tid < BM) {
        int r = row0 + tid;
        int t = r >> shift;
        int j = r & ((1 << shift) - 1);
        lbase[tid] = (t * NPTn + choff + 2 * j) * Hn;
    }
    __syncthreads();

    const float* Bptr;
    int ldb, bcol;
    if (col0 < 256) { Bptr = Ufw;  ldb = 256; bcol = col0; }
    else            { Bptr = Uiou; ldb = 384; bcol = col0 - 256; }

    int ty = tid >> 4, tx = tid & 15;
    unsigned long long acc[MT][4];
#pragma unroll
    for (int i = 0; i < MT; i++)
#pragma unroll
        for (int p = 0; p < 4; p++) acc[i][p] = 0ull;

    for (int kk = 0; kk < 2 * Hn; kk += BKf) {
#pragma unroll
        for (int e = tid; e < BM * (BKf / 4); e += 256) {
            int m  = e >> 3;
            int kq = (e & 7) * 4;
            float4 v = *(const float4*)(g_h + lbase[m] + kk + kq);
            float2* dst = As2 + m * BKf + kq;
            *(float4*)(dst)     = make_float4(v.x, v.x, v.y, v.y);
            *(float4*)(dst + 2) = make_float4(v.z, v.z, v.w, v.w);
        }
#pragma unroll
        for (int e = tid; e < BKf * (BNf / 4); e += 256) {
            int k = e >> 5;
            int c = (e & 31) * 4;
            *(float4*)(Bs + k * BNf + c) = *(const float4*)(Bptr + (kk + k) * ldb + bcol + c);
        }
        __syncthreads();

        const unsigned long long* Au = (const unsigned long long*)As2;
#pragma unroll
        for (int k = 0; k < BKf; k++) {
            ulonglong2 b0 = *(const ulonglong2*)(Bs + k * BNf + tx * 8);
            ulonglong2 b1 = *(const ulonglong2*)(Bs + k * BNf + tx * 8 + 4);
#pragma unroll
            for (int i = 0; i < MT; i++) {
                unsigned long long a = Au[(ty * MT + i) * BKf + k];
                FMA_F32X2(acc[i][0], a, b0.x, acc[i][0]);
                FMA_F32X2(acc[i][1], a, b0.y, acc[i][1]);
                FMA_F32X2(acc[i][2], a, b1.x, acc[i][2]);
                FMA_F32X2(acc[i][3], a, b1.y, acc[i][3]);
            }
        }
        __syncthreads();
    }
#pragma unroll
    for (int i = 0; i < MT; i++) {
        int r = row0 + ty * MT + i;
        float* drow = g_scratch + (size_t)r * 640 + col0 + tx * 8;
        union { unsigned long long u[2]; float4 f; } cv;
        cv.u[0] = acc[i][0]; cv.u[1] = acc[i][1];
        *(float4*)(drow) = cv.f;
        cv.u[0] = acc[i][2]; cv.u[1] = acc[i][3];
        *(float4*)(drow + 4) = cv.f;
    }
}

// ======================= Applies =======================
__global__ __launch_bounds__(256) void leaf_apply(const float* __restrict__ b_iou) {
    int idx = blockIdx.x * 256 + threadIdx.x;
    int r = idx >> 7, d = idx & 127;
    int node = (r >> 9) * NPTn + (r & 511);
    const float* s = g_scratch + (size_t)r * 384;
    float gi = s[d]       + b_iou[d];
    float go = s[128 + d] + b_iou[128 + d];
    float gu = s[256 + d] + b_iou[256 + d];
    float cc = sigm(gi) * tanhf(gu);
    g_c[node * Hn + d] = cc;
    g_h[node * Hn + d] = sigm(go) * tanhf(cc);
}

__global__ __launch_bounds__(256) void level_apply(const float* __restrict__ b_iou,
                                                   const float* __restrict__ Ufb,
                                                   int shift, int off, int choff) {
    int idx = blockIdx.x * 256 + threadIdx.x;
    int r = idx >> 7, d = idx & 127;
    int t = r >> shift;
    int j = r & ((1 << shift) - 1);
    int tb = t * NPTn;
    int node = tb + off + j;
    int left = tb + choff + 2 * j;
    const float* s = g_scratch + (size_t)r * 640;
    float fl = sigm(s[d]       + Ufb[d]);
    float fr = sigm(s[128 + d] + Ufb[128 + d]);
    float cred = fl * g_c[left * Hn + d] + fr * g_c[(left + 1) * Hn + d];
    float gi = s[256 + d] + b_iou[d];
    float go = s[384 + d] + b_iou[128 + d];
    float gu = s[512 + d] + b_iou[256 + d];
    float cc = sigm(gi) * tanhf(gu) + cred;
    g_c[node * Hn + d] = cc;
    g_h[node * Hn + d] = sigm(go) * tanhf(cc);
}

// Root projection + log_softmax. grid 128 (trees), block 128 (out dims).
__global__ __launch_bounds__(128) void final_kernel(const float* __restrict__ W,
                                                    const float* __restrict__ b,
                                                    float* __restrict__ out) {
    __shared__ float hr[128];
    __shared__ float red[128];
    int t = blockIdx.x, o = threadIdx.x;
    hr[o] = g_h[(t * NPTn + NPTn - 1) * Hn + o];
    __syncthreads();
    float acc = b[o];
#pragma unroll 8
    for (int k = 0; k < 128; k++) acc += hr[k] * W[k * 128 + o];
    red[o] = acc;
    __syncthreads();
#pragma unroll
    for (int s = 64; s > 0; s >>= 1) {
        if (o < s) red[o] = fmaxf(red[o], red[o + s]);
        __syncthreads();
    }
    float mx = red[0];
    __syncthreads();
    red[o] = expf(acc - mx);
    __syncthreads();
#pragma unroll
    for (int s = 64; s > 0; s >>= 1) {
        if (o < s) red[o] += red[o + s];
        __syncthreads();
    }
    out[t * 128 + o] = acc - mx - logf(red[0]);
}

// ---------------------------------------------------------------------------
// Inputs (metadata order): label, emb, W_iou, U_iou, b_iou, U_f_w, U_f_b, W_out, b_out
// ---------------------------------------------------------------------------
extern "C" void kernel_launch(void* const* d_in, const int* in_sizes, int n_in,
                              void* d_out, int out_size) {
    const int*   label = (const int*)  d_in[0];
    const float* emb   = (const float*)d_in[1];
    const float* W_iou = (const float*)d_in[2];
    const float* U_iou = (const float*)d_in[3];
    const float* b_iou = (const float*)d_in[4];
    const float* U_f_w = (const float*)d_in[5];
    const float* U_f_b = (const float*)d_in[6];
    const float* W_out = (const float*)d_in[7];
    const float* b_out = (const float*)d_in[8];
    float* out = (float*)d_out;

    leaf_gemm_f2<<<dim3(NLEAF / 64, 3), 256>>>(label, emb, W_iou);
    leaf_apply<<<(NLEAF * Hn) / 256, 256>>>(b_iou);

    for (int shift = 8; shift >= 0; shift--) {
        int cnt   = 1 << shift;                 // 256 .. 1
        int off   = NPTn - (2 * cnt - 1);
        int choff = NPTn - (4 * cnt - 1);
        int nd    = Bn * cnt;
        if (nd >= 2048)
            level_gemm_f2<4><<<dim3(nd / 64, 5), 256>>>(U_f_w, U_iou, shift, choff);
        else
            level_gemm_f2<2><<<dim3(nd / 32, 5), 256>>>(U_f_w, U_iou, shift, choff);
        level_apply<<<(nd * Hn) / 256, 256>>>(b_iou, U_f_b, shift, off, choff);
    }

    final_kernel<<<Bn, 128>>>(W_out, b_out, out);
}

// round 8
// speedup vs baseline: 2.5717x; 2.5717x over previous
#include <cuda_runtime.h>
#include <cstdint>

// Problem constants
#define Hn    128
#define Ln    512
#define Bn    128
#define NPTn  1023                 // 2L-1 nodes per tree
#define NTOT  (Bn * NPTn)          // 130944 nodes
#define NLEAF (Bn * Ln)            // 65536 leaves

// Persistent device state (no allocation allowed)
__device__ float g_h[NTOT * Hn];                 // 67 MB
__device__ float g_c[NTOT * Hn];                 // 67 MB
__device__ float g_scratch[NLEAF * 384];         // levels use stride 640 (20.9M < 25.2M floats)
__device__ float g_WT[640 * 256];                // [Ufw | Uiou]^T, tf32-rounded, [n][k] K-major
__device__ float g_WioT[384 * 128];              // W_iou^T, tf32-rounded

__device__ __forceinline__ float sigm(float x) { return 1.0f / (1.0f + expf(-x)); }

__device__ __forceinline__ float tf32r(float x) {
    float r; asm("cvt.rna.tf32.f32 %0, %1;" : "=f"(r) : "f"(x)); return r;
}

// m16n8k8 tf32 MMA (legacy HMMA path — valid on plain compute_103 PTX)
__device__ __forceinline__ void mma_tf32(float& c0, float& c1, float& c2, float& c3,
                                         uint32_t a0, uint32_t a1, uint32_t a2, uint32_t a3,
                                         uint32_t b0, uint32_t b1) {
    asm volatile(
        "mma.sync.aligned.m16n8k8.row.col.f32.tf32.tf32.f32 "
        "{%0,%1,%2,%3}, {%4,%5,%6,%7}, {%8,%9}, {%0,%1,%2,%3};"
        : "+f"(c0), "+f"(c1), "+f"(c2), "+f"(c3)
        : "r"(a0), "r"(a1), "r"(a2), "r"(a3), "r"(b0), "r"(b1));
}

// ---------------------------------------------------------------------------
// Weight pre-transpose (+ tf32 rounding), once per launch.
// ---------------------------------------------------------------------------
__global__ __launch_bounds__(256) void prep_WT(const float* __restrict__ Ufw,
                                               const float* __restrict__ Uiou) {
    int idx = blockIdx.x * 256 + threadIdx.x;         // 640*256
    if (idx >= 640 * 256) return;
    int n = idx >> 8, k = idx & 255;
    float v = (n < 256) ? Ufw[k * 256 + n] : Uiou[k * 384 + (n - 256)];
    g_WT[idx] = tf32r(v);
}
__global__ __launch_bounds__(256) void prep_WioT(const float* __restrict__ Wiou) {
    int idx = blockIdx.x * 256 + threadIdx.x;         // 384*128
    if (idx >= 384 * 128) return;
    int n = idx >> 7, k = idx & 127;
    g_WioT[idx] = tf32r(Wiou[k * 384 + n]);
}

// ---------------------------------------------------------------------------
// tf32 mma.sync GEMM. CTA tile 128(M) x 64(N), K staged 32/chunk in smem.
// 8 warps in 4(M) x 2(N) grid; warp tile 32x32 = 2 x 4 m16n8 mma tiles.
// Smem rows padded to 36 floats: fragment-load banks = (4*grp+qid)%32, all
// distinct -> conflict-free; 36 % 4 == 0 keeps float4 staging aligned.
// LEAF:  A row = emb[label[node]] (K=128), B = g_WioT, scratch stride 384.
// LEVEL: A row = 256 contiguous floats of g_h at child base, B = g_WT, 640.
// ---------------------------------------------------------------------------
#define PAD 36

template <int KTOT, int LDSCR, bool LEAF>
__global__ __launch_bounds__(256)
void gemm_mma(const float* __restrict__ Asrc, const int* __restrict__ label,
              int shift, int choff) {
    __shared__ float As[128 * PAD];      // 18 KB
    __shared__ float Bs[64 * PAD];       //  9 KB
    __shared__ int abase[128];

    const float* Ap = LEAF ? Asrc : g_h;
    const float* BT = LEAF ? g_WioT : g_WT;

    int tid  = threadIdx.x;
    int wid  = tid >> 5, lane = tid & 31;
    int grp  = lane >> 2, qid = lane & 3;
    int row0 = blockIdx.x * 128;
    int col0 = blockIdx.y * 64;
    int wm0  = (wid >> 1) * 32;          // warp M offset in tile
    int wn0  = (wid & 1) * 32;           // warp N offset in tile

    if (tid < 128) {
        int r = row0 + tid;
        int base;
        if (LEAF) {
            int g = (r >> 9) * NPTn + (r & 511);
            base = label[g] * Hn;
        } else {
            int t = r >> shift, j = r & ((1 << shift) - 1);
            base = (t * NPTn + choff + 2 * j) * Hn;
        }
        abase[tid] = base;
    }
    __syncthreads();

    float acc[2][4][4];                  // [mt][nt][reg]
#pragma unroll
    for (int mt = 0; mt < 2; mt++)
#pragma unroll
        for (int nt = 0; nt < 4; nt++)
#pragma unroll
            for (int p = 0; p < 4; p++) acc[mt][nt][p] = 0.0f;

    const uint32_t* Asu = (const uint32_t*)As;
    const uint32_t* Bsu = (const uint32_t*)Bs;

    for (int kk = 0; kk < KTOT; kk += 32) {
        // Stage A: 128 rows x 32 floats (tf32-rounded)
#pragma unroll
        for (int e = 0; e < 4; e++) {
            int i = tid + e * 256;                  // 0..1023
            int m = i >> 3, q = i & 7;
            float4 v = *(const float4*)(Ap + abase[m] + kk + q * 4);
            v.x = tf32r(v.x); v.y = tf32r(v.y); v.z = tf32r(v.z); v.w = tf32r(v.w);
            *(float4*)(As + m * PAD + q * 4) = v;
        }
        // Stage B: 64 rows x 32 floats (already tf32-rounded)
#pragma unroll
        for (int e = 0; e < 2; e++) {
            int i = tid + e * 256;                  // 0..511
            int n = i >> 3, q = i & 7;
            *(float4*)(Bs + n * PAD + q * 4) =
                *(const float4*)(BT + (size_t)(col0 + n) * KTOT + kk + q * 4);
        }
        __syncthreads();

#pragma unroll
        for (int ks = 0; ks < 4; ks++) {
            int k0 = ks * 8;
            uint32_t a[2][4];
#pragma unroll
            for (int mt = 0; mt < 2; mt++) {
                int base = (wm0 + mt * 16 + grp) * PAD + k0 + qid;
                a[mt][0] = Asu[base];
                a[mt][1] = Asu[base + 8 * PAD];
                a[mt][2] = Asu[base + 4];
                a[mt][3] = Asu[base + 8 * PAD + 4];
            }
            uint32_t b[4][2];
#pragma unroll
            for (int nt = 0; nt < 4; nt++) {
                int base = (wn0 + nt * 8 + grp) * PAD + k0 + qid;
                b[nt][0] = Bsu[base];
                b[nt][1] = Bsu[base + 4];
            }
#pragma unroll
            for (int mt = 0; mt < 2; mt++)
#pragma unroll
                for (int nt = 0; nt < 4; nt++)
                    mma_tf32(acc[mt][nt][0], acc[mt][nt][1], acc[mt][nt][2], acc[mt][nt][3],
                             a[mt][0], a[mt][1], a[mt][2], a[mt][3],
                             b[nt][0], b[nt][1]);
        }
        __syncthreads();
    }

    // Epilogue: c0,c1 at (row, 2*qid), c2,c3 at (row+8, 2*qid)
#pragma unroll
    for (int mt = 0; mt < 2; mt++) {
        int r = row0 + wm0 + mt * 16 + grp;
#pragma unroll
        for (int nt = 0; nt < 4; nt++) {
            int c = col0 + wn0 + nt * 8 + 2 * qid;
            *(float2*)(g_scratch + (size_t)r * LDSCR + c) =
                make_float2(acc[mt][nt][0], acc[mt][nt][1]);
            *(float2*)(g_scratch + (size_t)(r + 8) * LDSCR + c) =
                make_float2(acc[mt][nt][2], acc[mt][nt][3]);
        }
    }
}

// ======================= Applies =======================
__global__ __launch_bounds__(256) void leaf_apply(const float* __restrict__ b_iou) {
    int idx = blockIdx.x * 256 + threadIdx.x;
    int r = idx >> 7, d = idx & 127;
    int node = (r >> 9) * NPTn + (r & 511);
    const float* s = g_scratch + (size_t)r * 384;
    float gi = s[d]       + b_iou[d];
    float go = s[128 + d] + b_iou[128 + d];
    float gu = s[256 + d] + b_iou[256 + d];
    float cc = sigm(gi) * tanhf(gu);
    g_c[node * Hn + d] = cc;
    g_h[node * Hn + d] = sigm(go) * tanhf(cc);
}

__global__ __launch_bounds__(256) void level_apply(const float* __restrict__ b_iou,
                                                   const float* __restrict__ Ufb,
                                                   int shift, int off, int choff) {
    int idx = blockIdx.x * 256 + threadIdx.x;
    int r = idx >> 7, d = idx & 127;
    int t = r >> shift;
    int j = r & ((1 << shift) - 1);
    int tb = t * NPTn;
    int node = tb + off + j;
    int left = tb + choff + 2 * j;
    const float* s = g_scratch + (size_t)r * 640;
    float fl = sigm(s[d]       + Ufb[d]);
    float fr = sigm(s[128 + d] + Ufb[128 + d]);
    float cred = fl * g_c[left * Hn + d] + fr * g_c[(left + 1) * Hn + d];
    float gi = s[256 + d] + b_iou[d];
    float go = s[384 + d] + b_iou[128 + d];
    float gu = s[512 + d] + b_iou[256 + d];
    float cc = sigm(gi) * tanhf(gu) + cred;
    g_c[node * Hn + d] = cc;
    g_h[node * Hn + d] = sigm(go) * tanhf(cc);
}

// Root projection + log_softmax. grid 128 (trees), block 128 (out dims).
__global__ __launch_bounds__(128) void final_kernel(const float* __restrict__ W,
                                                    const float* __restrict__ b,
                                                    float* __restrict__ out) {
    __shared__ float hr[128];
    __shared__ float red[128];
    int t = blockIdx.x, o = threadIdx.x;
    hr[o] = g_h[(t * NPTn + NPTn - 1) * Hn + o];
    __syncthreads();
    float acc = b[o];
#pragma unroll 8
    for (int k = 0; k < 128; k++) acc += hr[k] * W[k * 128 + o];
    red[o] = acc;
    __syncthreads();
#pragma unroll
    for (int s = 64; s > 0; s >>= 1) {
        if (o < s) red[o] = fmaxf(red[o], red[o + s]);
        __syncthreads();
    }
    float mx = red[0];
    __syncthreads();
    red[o] = expf(acc - mx);
    __syncthreads();
#pragma unroll
    for (int s = 64; s > 0; s >>= 1) {
        if (o < s) red[o] += red[o + s];
        __syncthreads();
    }
    out[t * 128 + o] = acc - mx - logf(red[0]);
}

// ---------------------------------------------------------------------------
// Inputs (metadata order): label, emb, W_iou, U_iou, b_iou, U_f_w, U_f_b, W_out, b_out
// ---------------------------------------------------------------------------
extern "C" void kernel_launch(void* const* d_in, const int* in_sizes, int n_in,
                              void* d_out, int out_size) {
    const int*   label = (const int*)  d_in[0];
    const float* emb   = (const float*)d_in[1];
    const float* W_iou = (const float*)d_in[2];
    const float* U_iou = (const float*)d_in[3];
    const float* b_iou = (const float*)d_in[4];
    const float* U_f_w = (const float*)d_in[5];
    const float* U_f_b = (const float*)d_in[6];
    const float* W_out = (const float*)d_in[7];
    const float* b_out = (const float*)d_in[8];
    float* out = (float*)d_out;

    prep_WT<<<640, 256>>>(U_f_w, U_iou);
    prep_WioT<<<192, 256>>>(W_iou);

    // Leaves: [65536, 128] @ [128, 384]
    gemm_mma<128, 384, true><<<dim3(NLEAF / 128, 6), 256>>>(emb, label, 0, 0);
    leaf_apply<<<(NLEAF * Hn) / 256, 256>>>(b_iou);

    for (int shift = 8; shift >= 0; shift--) {
        int cnt   = 1 << shift;                 // 256 .. 1
        int off   = NPTn - (2 * cnt - 1);
        int choff = NPTn - (4 * cnt - 1);
        int nd    = Bn * cnt;                   // multiples of 128
        gemm_mma<256, 640, false><<<dim3(nd / 128, 10), 256>>>(nullptr, nullptr, shift, choff);
        level_apply<<<(nd * Hn) / 256, 256>>>(b_iou, U_f_b, shift, off, choff);
    }

    final_kernel<<<Bn, 128>>>(W_out, b_out, out);
}

// round 10
// speedup vs baseline: 2.8995x; 1.1275x over previous
#include <cuda_runtime.h>
#include <cstdint>

// Problem constants
#define Hn    128
#define Ln    512
#define Bn    128
#define NPTn  1023                 // 2L-1 nodes per tree
#define NTOT  (Bn * NPTn)          // 130944 nodes
#define NLEAF (Bn * Ln)            // 65536 leaves

// Persistent device state (no allocation allowed)
__device__ float g_h[NTOT * Hn];                 // 67 MB
__device__ float g_c[NTOT * Hn];                 // 67 MB
__device__ float g_WT[640 * 256];                // permuted [Ufw|Uiou]^T, tf32, [c][k], c=d*5+g
__device__ float g_WioT[384 * 128];              // permuted W_iou^T, tf32, [c][k], c=d*3+g

__device__ __forceinline__ float sigm(float x) { return 1.0f / (1.0f + expf(-x)); }

__device__ __forceinline__ float tf32r(float x) {
    float r; asm("cvt.rna.tf32.f32 %0, %1;" : "=f"(r) : "f"(x)); return r;
}

// m16n8k8 tf32 MMA (legacy HMMA path — valid on plain compute_103 PTX)
__device__ __forceinline__ void mma_tf32(float& c0, float& c1, float& c2, float& c3,
                                         uint32_t a0, uint32_t a1, uint32_t a2, uint32_t a3,
                                         uint32_t b0, uint32_t b1) {
    asm volatile(
        "mma.sync.aligned.m16n8k8.row.col.f32.tf32.tf32.f32 "
        "{%0,%1,%2,%3}, {%4,%5,%6,%7}, {%8,%9}, {%0,%1,%2,%3};"
        : "+f"(c0), "+f"(c1), "+f"(c2), "+f"(c3)
        : "r"(a0), "r"(a1), "r"(a2), "r"(a3), "r"(b0), "r"(b1));
}

// ---------------------------------------------------------------------------
// Weight pre-transpose into gate-interleaved K-major layout (+ tf32 round).
// Level: c = d*5 + g: g0=Ufw[:,d] g1=Ufw[:,128+d] g2=Uiou[:,d] g3=Uiou[:,128+d] g4=Uiou[:,256+d]
// Leaf:  c = d*3 + g: g0=Wiou[:,d] g1=Wiou[:,128+d] g2=Wiou[:,256+d]
// ---------------------------------------------------------------------------
__global__ __launch_bounds__(256) void prep_WT(const float* __restrict__ Ufw,
                                               const float* __restrict__ Uiou) {
    int idx = blockIdx.x * 256 + threadIdx.x;         // 640*256
    if (idx >= 640 * 256) return;
    int c = idx >> 8, k = idx & 255;
    int d = c / 5, g = c % 5;
    float v;
    if (g == 0)      v = Ufw[k * 256 + d];
    else if (g == 1) v = Ufw[k * 256 + 128 + d];
    else             v = Uiou[k * 384 + (g - 2) * 128 + d];
    g_WT[idx] = tf32r(v);
}
__global__ __launch_bounds__(256) void prep_WioT(const float* __restrict__ Wiou) {
    int idx = blockIdx.x * 256 + threadIdx.x;         // 384*128
    if (idx >= 384 * 128) return;
    int c = idx >> 7, k = idx & 127;
    int d = c / 3, g = c % 3;
    g_WioT[idx] = tf32r(Wiou[k * 384 + g * 128 + d]);
}

// ---------------------------------------------------------------------------
// Fused GEMM + LSTM-cell-apply.
// CTA tile CM(M) x NCOLS(N, gate-interleaved), K staged 32/chunk (PAD 36).
// 8 warps: 2 M-warps x 4 N-warps. After mainloop, acc -> SMEM (stride OST,
// coprime with 32), then apply reads the GATES consecutive gate values per
// (row, d) from SMEM and writes g_h/g_c directly. No scratch gmem.
// LEAF:  A row = emb[label[node]] (K=128), B = g_WioT, NCOLS=96  (3 gates x 32 d)
// LEVEL: A row = 256 floats of g_h at child base, B = g_WT, NCOLS=160 (5 x 32)
// ---------------------------------------------------------------------------
#define PAD 36

template <int CM, int NCOLS, int KTOT, int GATES, int OST, bool LEAF>
__global__ __launch_bounds__(256, 2)
void fused_gemm(const float* __restrict__ Asrc, const int* __restrict__ label,
                const float* __restrict__ b_iou, const float* __restrict__ Ufb,
                int shift, int off, int choff) {
    const int MTT = CM / 32;           // m16 tiles per warp (2 M-warps)
    const int NTT = NCOLS / 32;        // n8 tiles per warp (4 N-warps)

    extern __shared__ float dyn[];     // max(CM*OST, (CM+NCOLS)*PAD) floats
    float* As  = dyn;                  // CM  x PAD
    float* Bs  = dyn + CM * PAD;       // NCOLS x PAD
    float* out = dyn;                  // CM x OST (aliases staging; used after)
    __shared__ int abase[CM];

    const float* Ap = LEAF ? Asrc : g_h;
    const float* BT = LEAF ? g_WioT : g_WT;

    int tid  = threadIdx.x;
    int wid  = tid >> 5, lane = tid & 31;
    int grp  = lane >> 2, qid = lane & 3;
    int row0 = blockIdx.x * CM;
    int col0 = blockIdx.y * NCOLS;     // permuted-column origin
    int wm0  = (wid >> 2) * (MTT * 16);
    int wn0  = (wid & 3) * (NTT * 8);

    if (tid < CM) {
        int r = row0 + tid;
        int base;
        if (LEAF) {
            int g = (r >> 9) * NPTn + (r & 511);
            base = label[g] * Hn;
        } else {
            int t = r >> shift, j = r & ((1 << shift) - 1);
            base = (t * NPTn + choff + 2 * j) * Hn;
        }
        abase[tid] = base;
    }
    __syncthreads();

    float acc[MTT][NTT][4];
#pragma unroll
    for (int mt = 0; mt < MTT; mt++)
#pragma unroll
        for (int nt = 0; nt < NTT; nt++)
#pragma unroll
            for (int p = 0; p < 4; p++) acc[mt][nt][p] = 0.0f;

    const uint32_t* Asu = (const uint32_t*)As;
    const uint32_t* Bsu = (const uint32_t*)Bs;

    for (int kk = 0; kk < KTOT; kk += 32) {
        __syncthreads();               // protect staging reuse across chunks
        // Stage A: CM rows x 32 floats (tf32-rounded)
#pragma unroll
        for (int e = 0; e < CM / 32; e++) {
            int i = tid + e * 256;
            int m = i >> 3, q = i & 7;
            float4 v = *(const float4*)(Ap + abase[m] + kk + q * 4);
            v.x = tf32r(v.x); v.y = tf32r(v.y); v.z = tf32r(v.z); v.w = tf32r(v.w);
            *(float4*)(As + m * PAD + q * 4) = v;
        }
        // Stage B: NCOLS rows x 32 floats (already tf32-rounded)
#pragma unroll
        for (int e = 0; e < NCOLS / 32; e++) {
            int i = tid + e * 256;
            int n = i >> 3, q = i & 7;
            *(float4*)(Bs + n * PAD + q * 4) =
                *(const float4*)(BT + (size_t)(col0 + n) * KTOT + kk + q * 4);
        }
        __syncthreads();

#pragma unroll
        for (int ks = 0; ks < 4; ks++) {
            int k0 = ks * 8;
            uint32_t a[MTT][4];
#pragma unroll
            for (int mt = 0; mt < MTT; mt++) {
                int base = (wm0 + mt * 16 + grp) * PAD + k0 + qid;
                a[mt][0] = Asu[base];
                a[mt][1] = Asu[base + 8 * PAD];
                a[mt][2] = Asu[base + 4];
                a[mt][3] = Asu[base + 8 * PAD + 4];
            }
            uint32_t b[NTT][2];
#pragma unroll
            for (int nt = 0; nt < NTT; nt++) {
                int base = (wn0 + nt * 8 + grp) * PAD + k0 + qid;
                b[nt][0] = Bsu[base];
                b[nt][1] = Bsu[base + 4];
            }
#pragma unroll
            for (int mt = 0; mt < MTT; mt++)
#pragma unroll
                for (int nt = 0; nt < NTT; nt++)
                    mma_tf32(acc[mt][nt][0], acc[mt][nt][1], acc[mt][nt][2], acc[mt][nt][3],
                             a[mt][0], a[mt][1], a[mt][2], a[mt][3],
                             b[nt][0], b[nt][1]);
        }
    }

    // acc -> SMEM out buffer
    __syncthreads();
#pragma unroll
    for (int mt = 0; mt < MTT; mt++) {
        int r = wm0 + mt * 16 + grp;
#pragma unroll
        for (int nt = 0; nt < NTT; nt++) {
            int c = wn0 + nt * 8 + 2 * qid;
            out[r * OST + c]           = acc[mt][nt][0];
            out[r * OST + c + 1]       = acc[mt][nt][1];
            out[(r + 8) * OST + c]     = acc[mt][nt][2];
            out[(r + 8) * OST + c + 1] = acc[mt][nt][3];
        }
    }
    __syncthreads();

    // Apply phase: one (row, d) per item; d = tid&31 keeps gmem coalesced.
    int dgbase = blockIdx.y * 32;
#pragma unroll
    for (int item = tid; item < CM * 32; item += 256) {
        int d   = item & 31;
        int row = item >> 5;
        int R   = row0 + row;
        int dg  = dgbase + d;
        const float* s = out + row * OST + d * GATES;
        if (LEAF) {
            int node = (R >> 9) * NPTn + (R & 511);
            float gi = s[0] + b_iou[dg];
            float go = s[1] + b_iou[128 + dg];
            float gu = s[2] + b_iou[256 + dg];
            float cc = sigm(gi) * tanhf(gu);
            g_c[node * Hn + dg] = cc;
            g_h[node * Hn + dg] = sigm(go) * tanhf(cc);
        } else {
            int t = R >> shift, j = R & ((1 << shift) - 1);
            int tb = t * NPTn;
            int node = tb + off + j;
            int left = tb + choff + 2 * j;
            float fl = sigm(s[0] + Ufb[dg]);
            float fr = sigm(s[1] + Ufb[128 + dg]);
            float cred = fl * g_c[left * Hn + dg] + fr * g_c[(left + 1) * Hn + dg];
            float gi = s[2] + b_iou[dg];
            float go = s[3] + b_iou[128 + dg];
            float gu = s[4] + b_iou[256 + dg];
            float cc = sigm(gi) * tanhf(gu) + cred;
            g_c[node * Hn + dg] = cc;
            g_h[node * Hn + dg] = sigm(go) * tanhf(cc);
        }
    }
}

// Root projection + log_softmax. grid 128 (trees), block 128 (out dims).
__global__ __launch_bounds__(128) void final_kernel(const float* __restrict__ W,
                                                    const float* __restrict__ b,
                                                    float* __restrict__ out) {
    __shared__ float hr[128];
    __shared__ float red[128];
    int t = blockIdx.x, o = threadIdx.x;
    hr[o] = g_h[(t * NPTn + NPTn - 1) * Hn + o];
    __syncthreads();
    float acc = b[o];
#pragma unroll 8
    for (int k = 0; k < 128; k++) acc += hr[k] * W[k * 128 + o];
    red[o] = acc;
    __syncthreads();
#pragma unroll
    for (int s = 64; s > 0; s >>= 1) {
        if (o < s) red[o] = fmaxf(red[o], red[o + s]);
        __syncthreads();
    }
    float mx = red[0];
    __syncthreads();
    red[o] = expf(acc - mx);
    __syncthreads();
#pragma unroll
    for (int s = 64; s > 0; s >>= 1) {
        if (o < s) red[o] += red[o + s];
        __syncthreads();
    }
    out[t * 128 + o] = acc - mx - logf(red[0]);
}

// ---------------------------------------------------------------------------
// Inputs (metadata order): label, emb, W_iou, U_iou, b_iou, U_f_w, U_f_b, W_out, b_out
// ---------------------------------------------------------------------------
// Instantiations: leaf CM=128 NCOLS=96 K=128; level big CM=128 NCOLS=160 K=256;
// level tail CM=32.
#define LEAF_SMEM  (128 * 99 * 4)                  // 50688 B (> staging 32256)
#define LV128_SMEM (128 * 165 * 4)                 // 84480 B (> staging 41472)
#define LV32_SMEM  ((32 + 160) * PAD * 4)          // 27648 B (> out 21120)

extern "C" void kernel_launch(void* const* d_in, const int* in_sizes, int n_in,
                              void* d_out, int out_size) {
    const int*   label = (const int*)  d_in[0];
    const float* emb   = (const float*)d_in[1];
    const float* W_iou = (const float*)d_in[2];
    const float* U_iou = (const float*)d_in[3];
    const float* b_iou = (const float*)d_in[4];
    const float* U_f_w = (const float*)d_in[5];
    const float* U_f_b = (const float*)d_in[6];
    const float* W_out = (const float*)d_in[7];
    const float* b_out = (const float*)d_in[8];
    float* out = (float*)d_out;

    cudaFuncSetAttribute((const void*)fused_gemm<128, 96, 128, 3, 99, true>,
                         cudaFuncAttributeMaxDynamicSharedMemorySize, LEAF_SMEM);
    cudaFuncSetAttribute((const void*)fused_gemm<128, 160, 256, 5, 165, false>,
                         cudaFuncAttributeMaxDynamicSharedMemorySize, LV128_SMEM);
    cudaFuncSetAttribute((const void*)fused_gemm<32, 160, 256, 5, 165, false>,
                         cudaFuncAttributeMaxDynamicSharedMemorySize, LV32_SMEM);

    prep_WT<<<640, 256>>>(U_f_w, U_iou);
    prep_WioT<<<192, 256>>>(W_iou);

    // Leaves: fused [65536,128]@[128,384(permuted)] + cell update
    fused_gemm<128, 96, 128, 3, 99, true>
        <<<dim3(NLEAF / 128, 4), 256, LEAF_SMEM>>>(emb, label, b_iou, nullptr, 0, 0, 0);

    for (int shift = 8; shift >= 0; shift--) {
        int cnt   = 1 << shift;                 // 256 .. 1
        int off   = NPTn - (2 * cnt - 1);
        int choff = NPTn - (4 * cnt - 1);
        int nd    = Bn * cnt;                   // 32768 .. 128
        if (nd >= 8192)
            fused_gemm<128, 160, 256, 5, 165, false>
                <<<dim3(nd / 128, 4), 256, LV128_SMEM>>>(nullptr, nullptr, b_iou, U_f_b,
                                                         shift, off, choff);
        else
            fused_gemm<32, 160, 256, 5, 165, false>
                <<<dim3(nd / 32, 4), 256, LV32_SMEM>>>(nullptr, nullptr, b_iou, U_f_b,
                                                       shift, off, choff);
    }

    final_kernel<<<Bn, 128>>>(W_out, b_out, out);
}

// round 12
// speedup vs baseline: 3.5444x; 1.2224x over previous
#include <cuda_runtime.h>
#include <cuda_bf16.h>
#include <cstdint>

// Problem constants
#define Hn    128
#define Ln    512
#define Bn    128
#define NPTn  1023                 // 2L-1 nodes per tree
#define NTOT  (Bn * NPTn)          // 130944 nodes
#define NLEAF (Bn * Ln)            // 65536 leaves

// Persistent device state (no allocation allowed)
__device__ float g_h[NTOT * Hn];                       // 67 MB
__device__ float g_c[NTOT * Hn];                       // 67 MB
__device__ __nv_bfloat16 g_WTb[640 * 256];             // permuted [Ufw|Uiou]^T, bf16, [c][k], c=d*5+g
__device__ __nv_bfloat16 g_WioTb[384 * 128];           // permuted W_iou^T, bf16, [c][k], c=d*3+g

__device__ __forceinline__ float sigm(float x) { return 1.0f / (1.0f + expf(-x)); }

__device__ __forceinline__ uint32_t packbf(float a, float b) {
    __nv_bfloat162 t = __floats2bfloat162_rn(a, b);
    return *(uint32_t*)&t;
}

// m16n8k16 bf16 MMA, fp32 accum (legacy HMMA path — valid on plain compute_103)
__device__ __forceinline__ void mma_bf16(float& c0, float& c1, float& c2, float& c3,
                                         uint32_t a0, uint32_t a1, uint32_t a2, uint32_t a3,
                                         uint32_t b0, uint32_t b1) {
    asm volatile(
        "mma.sync.aligned.m16n8k16.row.col.f32.bf16.bf16.f32 "
        "{%0,%1,%2,%3}, {%4,%5,%6,%7}, {%8,%9}, {%0,%1,%2,%3};"
        : "+f"(c0), "+f"(c1), "+f"(c2), "+f"(c3)
        : "r"(a0), "r"(a1), "r"(a2), "r"(a3), "r"(b0), "r"(b1));
}

// ---------------------------------------------------------------------------
// Weight pre-transpose into gate-interleaved K-major bf16 layout.
// Level: c = d*5 + g (g0=Ufw[:,d], g1=Ufw[:,128+d], g2..4=Uiou[:,{0,128,256}+d])
// Leaf:  c = d*3 + g (g=Wiou[:, g*128+d])
// ---------------------------------------------------------------------------
__global__ __launch_bounds__(256) void prep_WT(const float* __restrict__ Ufw,
                                               const float* __restrict__ Uiou) {
    int idx = blockIdx.x * 256 + threadIdx.x;         // 640*256
    if (idx >= 640 * 256) return;
    int c = idx >> 8, k = idx & 255;
    int d = c / 5, g = c % 5;
    float v;
    if (g == 0)      v = Ufw[k * 256 + d];
    else if (g == 1) v = Ufw[k * 256 + 128 + d];
    else             v = Uiou[k * 384 + (g - 2) * 128 + d];
    g_WTb[idx] = __float2bfloat16(v);
}
__global__ __launch_bounds__(256) void prep_WioT(const float* __restrict__ Wiou) {
    int idx = blockIdx.x * 256 + threadIdx.x;         // 384*128
    if (idx >= 384 * 128) return;
    int c = idx >> 7, k = idx & 127;
    int d = c / 3, g = c % 3;
    g_WioTb[idx] = __float2bfloat16(Wiou[k * 384 + g * 128 + d]);
}

// ---------------------------------------------------------------------------
// Fused bf16-MMA GEMM + LSTM-cell-apply. CTA tile CM x NCOLS (gate-interleaved),
// K staged 64/chunk as bf16 (row stride 72 bf16 = 36 words -> conflict-free
// fragment LDS). 8 warps: 4(M) x 2(N).
// After mainloop: acc -> SMEM out (stride OST), then cell update writes
// g_h/g_c directly. No scratch gmem.
// LEAF:  A row = emb[label[node]] (K=128), B = g_WioTb, NCOLS=96  (32 d x 3)
// LEVEL: A row = 256 floats of g_h at child base, B = g_WTb, NCOLS=80 (16 d x 5)
// ---------------------------------------------------------------------------
#define SAB 72            // bf16 per staged row
#define SABY 144          // bytes per staged row
#define SAW 36            // words per staged row

template <int CM, int NCOLS, int KTOT, int GATES, int OST, int MINB, bool LEAF>
__global__ __launch_bounds__(256, MINB)
void fused_gemm(const float* __restrict__ Asrc, const int* __restrict__ label,
                const float* __restrict__ b_iou, const float* __restrict__ Ufb,
                int shift, int off, int choff) {
    const int MTT = CM / 64;           // m16 tiles per warp (4 M-warps)
    const int NTT = NCOLS / 16;        // n8 tiles per warp  (2 N-warps)
    const int DN  = NCOLS / GATES;     // d's per CTA (32 leaf / 16 level)

    extern __shared__ float dyn[];
    __nv_bfloat16* As = (__nv_bfloat16*)dyn;          // CM x SAB
    __nv_bfloat16* Bs = As + CM * SAB;                // NCOLS x SAB
    float* out = dyn;                                 // CM x OST (aliases staging)
    __shared__ int abase[CM];

    const float* Ap = LEAF ? Asrc : g_h;
    const __nv_bfloat16* BT = LEAF ? g_WioTb : g_WTb;

    int tid  = threadIdx.x;
    int wid  = tid >> 5, lane = tid & 31;
    int grp  = lane >> 2, qid = lane & 3;
    int row0 = blockIdx.x * CM;
    int col0 = blockIdx.y * NCOLS;
    int wm0  = (wid >> 1) * (CM / 4);
    int wn0  = (wid & 1) * (NCOLS / 2);

    if (tid < CM) {
        int r = row0 + tid;
        int base;
        if (LEAF) {
            int g = (r >> 9) * NPTn + (r & 511);
            base = label[g] * Hn;
        } else {
            int t = r >> shift, j = r & ((1 << shift) - 1);
            base = (t * NPTn + choff + 2 * j) * Hn;
        }
        abase[tid] = base;
    }
    __syncthreads();

    float acc[MTT][NTT][4];
#pragma unroll
    for (int mt = 0; mt < MTT; mt++)
#pragma unroll
        for (int nt = 0; nt < NTT; nt++)
#pragma unroll
            for (int p = 0; p < 4; p++) acc[mt][nt][p] = 0.0f;

    const uint32_t* Asw = (const uint32_t*)As;
    const uint32_t* Bsw = (const uint32_t*)Bs;
    char* Ab = (char*)As;
    char* Bb = (char*)Bs;

    for (int kk = 0; kk < KTOT; kk += 64) {
        __syncthreads();               // staging buffer reuse across chunks
        // Stage A: CM rows x 64 floats -> bf16 pairs
#pragma unroll
        for (int e = 0; e < CM / 16; e++) {
            int i = tid + e * 256;
            int m = i >> 4, q = i & 15;                 // 16 float4 per row
            float4 v = *(const float4*)(Ap + abase[m] + kk + q * 4);
            uint2 u;
            u.x = packbf(v.x, v.y);
            u.y = packbf(v.z, v.w);
            *(uint2*)(Ab + m * SABY + q * 8) = u;
        }
        // Stage B: NCOLS rows x 64 bf16 (already bf16 in gmem)
#pragma unroll
        for (int e = 0; e < (NCOLS * 8 + 255) / 256; e++) {
            int i = tid + e * 256;                      // uint4 = 8 bf16
            if (i < NCOLS * 8) {
                int n = i >> 3, q = i & 7;
                uint4 v = *(const uint4*)(BT + (size_t)(col0 + n) * KTOT + kk + q * 8);
                *(uint4*)(Bb + n * SABY + q * 16) = v;
            }
        }
        __syncthreads();

#pragma unroll
        for (int ks = 0; ks < 4; ks++) {               // 4 x k16 = 64
            int k0w = ks * 8;                          // word offset
            uint32_t a[MTT][4];
#pragma unroll
            for (int mt = 0; mt < MTT; mt++) {
                int base = (wm0 + mt * 16 + grp) * SAW + k0w + qid;
                a[mt][0] = Asw[base];
                a[mt][1] = Asw[base + 8 * SAW];
                a[mt][2] = Asw[base + 4];
                a[mt][3] = Asw[base + 8 * SAW + 4];
            }
            uint32_t b[NTT][2];
#pragma unroll
            for (int nt = 0; nt < NTT; nt++) {
                int base = (wn0 + nt * 8 + grp) * SAW + k0w + qid;
                b[nt][0] = Bsw[base];
                b[nt][1] = Bsw[base + 4];
            }
#pragma unroll
            for (int mt = 0; mt < MTT; mt++)
#pragma unroll
                for (int nt = 0; nt < NTT; nt++)
                    mma_bf16(acc[mt][nt][0], acc[mt][nt][1], acc[mt][nt][2], acc[mt][nt][3],
                             a[mt][0], a[mt][1], a[mt][2], a[mt][3],
                             b[nt][0], b[nt][1]);
        }
    }

    // acc -> SMEM out buffer
    __syncthreads();
#pragma unroll
    for (int mt = 0; mt < MTT; mt++) {
        int r = wm0 + mt * 16 + grp;
#pragma unroll
        for (int nt = 0; nt < NTT; nt++) {
            int c = wn0 + nt * 8 + 2 * qid;
            out[r * OST + c]           = acc[mt][nt][0];
            out[r * OST + c + 1]       = acc[mt][nt][1];
            out[(r + 8) * OST + c]     = acc[mt][nt][2];
            out[(r + 8) * OST + c + 1] = acc[mt][nt][3];
        }
    }
    __syncthreads();

    // Apply phase: one (row, d) per item.
    int dgbase = blockIdx.y * DN;
#pragma unroll
    for (int item = tid; item < CM * DN; item += 256) {
        int d   = item & (DN - 1);
        int row = item / DN;
        int R   = row0 + row;
        int dg  = dgbase + d;
        const float* s = out + row * OST + d * GATES;
        if (LEAF) {
            int node = (R >> 9) * NPTn + (R & 511);
            float gi = s[0] + b_iou[dg];
            float go = s[1] + b_iou[128 + dg];
            float gu = s[2] + b_iou[256 + dg];
            float cc = sigm(gi) * tanhf(gu);
            g_c[node * Hn + dg] = cc;
            g_h[node * Hn + dg] = sigm(go) * tanhf(cc);
        } else {
            int t = R >> shift, j = R & ((1 << shift) - 1);
            int tb = t * NPTn;
            int node = tb + off + j;
            int left = tb + choff + 2 * j;
            float fl = sigm(s[0] + Ufb[dg]);
            float fr = sigm(s[1] + Ufb[128 + dg]);
            float cred = fl * g_c[left * Hn + dg] + fr * g_c[(left + 1) * Hn + dg];
            float gi = s[2] + b_iou[dg];
            float go = s[3] + b_iou[128 + dg];
            float gu = s[4] + b_iou[256 + dg];
            float cc = sigm(gi) * tanhf(gu) + cred;
            g_c[node * Hn + dg] = cc;
            g_h[node * Hn + dg] = sigm(go) * tanhf(cc);
        }
    }
}

// Root projection + log_softmax. grid 128 (trees), block 128 (out dims).
__global__ __launch_bounds__(128) void final_kernel(const float* __restrict__ W,
                                                    const float* __restrict__ b,
                                                    float* __restrict__ out) {
    __shared__ float hr[128];
    __shared__ float red[128];
    int t = blockIdx.x, o = threadIdx.x;
    hr[o] = g_h[(t * NPTn + NPTn - 1) * Hn + o];
    __syncthreads();
    float acc = b[o];
#pragma unroll 8
    for (int k = 0; k < 128; k++) acc += hr[k] * W[k * 128 + o];
    red[o] = acc;
    __syncthreads();
#pragma unroll
    for (int s = 64; s > 0; s >>= 1) {
        if (o < s) red[o] = fmaxf(red[o], red[o + s]);
        __syncthreads();
    }
    float mx = red[0];
    __syncthreads();
    red[o] = expf(acc - mx);
    __syncthreads();
#pragma unroll
    for (int s = 64; s > 0; s >>= 1) {
        if (o < s) red[o] += red[o + s];
        __syncthreads();
    }
    out[t * 128 + o] = acc - mx - logf(red[0]);
}

// ---------------------------------------------------------------------------
// Inputs (metadata order): label, emb, W_iou, U_iou, b_iou, U_f_w, U_f_b, W_out, b_out
// ---------------------------------------------------------------------------
// Dynamic smem (bytes): max(out, staging)
#define LEAF_SMEM  (128 * 96 * 4)                        // 49152 (> 32256 staging)
#define LV128_SMEM (128 * 80 * 4)                        // 40960 (> 29952 staging)
#define LV64_SMEM  ((64 + 80) * SABY)                    // 20736 (> 20480 out)

extern "C" void kernel_launch(void* const* d_in, const int* in_sizes, int n_in,
                              void* d_out, int out_size) {
    const int*   label = (const int*)  d_in[0];
    const float* emb   = (const float*)d_in[1];
    const float* W_iou = (const float*)d_in[2];
    const float* U_iou = (const float*)d_in[3];
    const float* b_iou = (const float*)d_in[4];
    const float* U_f_w = (const float*)d_in[5];
    const float* U_f_b = (const float*)d_in[6];
    const float* W_out = (const float*)d_in[7];
    const float* b_out = (const float*)d_in[8];
    float* out = (float*)d_out;

    // Opt-in dynamic smem (static abase[] pushes leaf total past 48 KB).
    // Host-side attribute set; proven capture-safe in R10.
    cudaFuncSetAttribute((const void*)fused_gemm<128, 96, 128, 3, 96, 2, true>,
                         cudaFuncAttributeMaxDynamicSharedMemorySize, LEAF_SMEM);
    cudaFuncSetAttribute((const void*)fused_gemm<128, 80, 256, 5, 80, 3, false>,
                         cudaFuncAttributeMaxDynamicSharedMemorySize, LV128_SMEM);
    cudaFuncSetAttribute((const void*)fused_gemm<64, 80, 256, 5, 80, 3, false>,
                         cudaFuncAttributeMaxDynamicSharedMemorySize, LV64_SMEM);

    prep_WT<<<640, 256>>>(U_f_w, U_iou);
    prep_WioT<<<192, 256>>>(W_iou);

    // Leaves: fused [65536,128]@[128,384(permuted)] + cell update
    fused_gemm<128, 96, 128, 3, 96, 2, true>
        <<<dim3(NLEAF / 128, 4), 256, LEAF_SMEM>>>(emb, label, b_iou, nullptr, 0, 0, 0);

    for (int shift = 8; shift >= 0; shift--) {
        int cnt   = 1 << shift;                 // 256 .. 1
        int off   = NPTn - (2 * cnt - 1);
        int choff = NPTn - (4 * cnt - 1);
        int nd    = Bn * cnt;                   // 32768 .. 128
        if (nd >= 8192)
            fused_gemm<128, 80, 256, 5, 80, 3, false>
                <<<dim3(nd / 128, 8), 256, LV128_SMEM>>>(nullptr, nullptr, b_iou, U_f_b,
                                                         shift, off, choff);
        else
            fused_gemm<64, 80, 256, 5, 80, 3, false>
                <<<dim3(nd / 64, 8), 256, LV64_SMEM>>>(nullptr, nullptr, b_iou, U_f_b,
                                                       shift, off, choff);
    }

    final_kernel<<<Bn, 128>>>(W_out, b_out, out);
}

// round 13
// speedup vs baseline: 5.4876x; 1.5483x over previous
#include <cuda_runtime.h>
#include <cuda_bf16.h>
#include <cstdint>

// Problem constants
#define Hn    128
#define Ln    512
#define Bn    128
#define VOCABn 32000
#define NPTn  1023                 // 2L-1 nodes per tree
#define NTOT  (Bn * NPTn)          // 130944 nodes
#define NLEAF (Bn * Ln)            // 65536 leaves

// Persistent device state (no allocation allowed)
__device__ float g_h[NTOT * Hn];                       // fp32 h (only roots written; final proj)
__device__ float g_c[NTOT * Hn];                       // fp32 c chain
__device__ __nv_bfloat16 g_hb[NTOT * Hn];              // bf16 h mirror (GEMM operand)
__device__ __nv_bfloat16 g_embB[VOCABn * Hn];          // bf16 emb
__device__ __nv_bfloat16 g_WTb[640 * 256];             // permuted [Ufw|Uiou]^T, bf16, [c][k], c=d*5+g
__device__ __nv_bfloat16 g_WioTb[384 * 128];           // permuted W_iou^T, bf16, [c][k], c=d*3+g

__device__ __forceinline__ float sigm(float x) { return 1.0f / (1.0f + expf(-x)); }

// m16n8k16 bf16 MMA, fp32 accum (legacy HMMA path — valid on plain compute_103)
__device__ __forceinline__ void mma_bf16(float& c0, float& c1, float& c2, float& c3,
                                         uint32_t a0, uint32_t a1, uint32_t a2, uint32_t a3,
                                         uint32_t b0, uint32_t b1) {
    asm volatile(
        "mma.sync.aligned.m16n8k16.row.col.f32.bf16.bf16.f32 "
        "{%0,%1,%2,%3}, {%4,%5,%6,%7}, {%8,%9}, {%0,%1,%2,%3};"
        : "+f"(c0), "+f"(c1), "+f"(c2), "+f"(c3)
        : "r"(a0), "r"(a1), "r"(a2), "r"(a3), "r"(b0), "r"(b1));
}

__device__ __forceinline__ uint32_t smem_u32(const void* p) {
    uint32_t a;
    asm("{ .reg .u64 t; cvta.to.shared.u64 t, %1; cvt.u32.u64 %0, t; }" : "=r"(a) : "l"(p));
    return a;
}
__device__ __forceinline__ void cpa16(uint32_t s, const void* g) {
    asm volatile("cp.async.cg.shared.global [%0], [%1], 16;" :: "r"(s), "l"(g));
}
#define CP_COMMIT() asm volatile("cp.async.commit_group;" ::: "memory")
#define CP_WAIT(N)  asm volatile("cp.async.wait_group %0;" :: "n"(N) : "memory")

// ---------------------------------------------------------------------------
// Prep kernels: weight transpose to gate-interleaved K-major bf16; emb -> bf16.
// Level: c = d*5 + g (g0=Ufw[:,d], g1=Ufw[:,128+d], g2..4=Uiou[:,{0,128,256}+d])
// Leaf:  c = d*3 + g (g=Wiou[:, g*128+d])
// ---------------------------------------------------------------------------
__global__ __launch_bounds__(256) void prep_WT(const float* __restrict__ Ufw,
                                               const float* __restrict__ Uiou) {
    int idx = blockIdx.x * 256 + threadIdx.x;
    if (idx >= 640 * 256) return;
    int c = idx >> 8, k = idx & 255;
    int d = c / 5, g = c % 5;
    float v;
    if (g == 0)      v = Ufw[k * 256 + d];
    else if (g == 1) v = Ufw[k * 256 + 128 + d];
    else             v = Uiou[k * 384 + (g - 2) * 128 + d];
    g_WTb[idx] = __float2bfloat16(v);
}
__global__ __launch_bounds__(256) void prep_WioT(const float* __restrict__ Wiou) {
    int idx = blockIdx.x * 256 + threadIdx.x;
    if (idx >= 384 * 128) return;
    int c = idx >> 7, k = idx & 127;
    int d = c / 3, g = c % 3;
    g_WioTb[idx] = __float2bfloat16(Wiou[k * 384 + g * 128 + d]);
}
__global__ __launch_bounds__(256) void prep_emb(const float* __restrict__ emb) {
    int idx = blockIdx.x * 256 + threadIdx.x;           // VOCABn*Hn
    float2 v = *(const float2*)(emb + idx * 2);
    __nv_bfloat162 t = __floats2bfloat162_rn(v.x, v.y);
    *(__nv_bfloat162*)(g_embB + idx * 2) = t;
}

// ---------------------------------------------------------------------------
// Fused bf16-MMA GEMM + LSTM-cell-apply, cp.async double-buffered staging.
// CTA tile CM x NCOLS (gate-interleaved cols), K in 64-wide chunks.
// Staged rows: 64 bf16 + pad = 72 bf16 (144 B) -> conflict-free scalar
// fragment LDS (word stride 36). 8 warps: 4(M) x 2(N).
// After mainloop: acc -> SMEM out (stride OST), apply writes g_c / g_hb
// (and fp32 g_h at the root level only). No scratch gmem.
// LEAF:  A = g_embB[label[node]] (K=128), B = g_WioTb, NCOLS=96 (32 d x 3)
// LEVEL: A = 256 bf16 of g_hb at child base (K=256), B = g_WTb, NCOLS=80 (16 d x 5)
// ---------------------------------------------------------------------------
#define SABY 144          // bytes per staged row
#define SAW 36            // words per staged row

template <int CM, int NCOLS, int KTOT, int GATES, int OST, int MINB, bool LEAF>
__global__ __launch_bounds__(256, MINB)
void fused_gemm(const int* __restrict__ label,
                const float* __restrict__ b_iou, const float* __restrict__ Ufb,
                int shift, int off, int choff) {
    const int MTT  = CM / 64;          // m16 tiles per warp (4 M-warps)
    const int NTT  = NCOLS / 16;       // n8 tiles per warp  (2 N-warps)
    const int DN   = NCOLS / GATES;    // d's per CTA
    const int NCH  = KTOT / 64;        // K chunks
    const int BUFB = (CM + NCOLS) * SABY;   // bytes per stage buffer

    extern __shared__ float dyn[];     // 2 stage buffers; out aliases from 0
    char*  dynb = (char*)dyn;
    float* out  = dyn;                 // CM x OST
    __shared__ int abase[CM];

    const __nv_bfloat16* Ab = LEAF ? g_embB : g_hb;
    const __nv_bfloat16* BT = LEAF ? g_WioTb : g_WTb;

    int tid  = threadIdx.x;
    int wid  = tid >> 5, lane = tid & 31;
    int grp  = lane >> 2, qid = lane & 3;
    int row0 = blockIdx.x * CM;
    int col0 = blockIdx.y * NCOLS;
    int wm0  = (wid >> 1) * (CM / 4);
    int wn0  = (wid & 1) * (NCOLS / 2);

    if (tid < CM) {
        int r = row0 + tid;
        int base;
        if (LEAF) {
            int g = (r >> 9) * NPTn + (r & 511);
            base = label[g] * Hn;
        } else {
            int t = r >> shift, j = r & ((1 << shift) - 1);
            base = (t * NPTn + choff + 2 * j) * Hn;
        }
        abase[tid] = base;
    }
    __syncthreads();

    uint32_t sbase = smem_u32(dynb);

    // Stage chunk (kk = bf16 offset) into buffer buf via cp.async.
    auto stage = [&](int kk, int buf) {
        uint32_t sb = sbase + buf * BUFB;
#pragma unroll
        for (int e = 0; e < CM / 32; e++) {          // CM*8 16B transfers
            int i = tid + e * 256;
            int m = i >> 3, q = i & 7;
            cpa16(sb + m * SABY + q * 16, Ab + abase[m] + kk + q * 8);
        }
#pragma unroll
        for (int e = 0; e < (NCOLS * 8 + 255) / 256; e++) {
            int i = tid + e * 256;
            if (i < NCOLS * 8) {
                int n = i >> 3, q = i & 7;
                cpa16(sb + CM * SABY + n * SABY + q * 16,
                      BT + (size_t)(col0 + n) * KTOT + kk + q * 8);
            }
        }
    };

    float acc[MTT][NTT][4];
#pragma unroll
    for (int mt = 0; mt < MTT; mt++)
#pragma unroll
        for (int nt = 0; nt < NTT; nt++)
#pragma unroll
            for (int p = 0; p < 4; p++) acc[mt][nt][p] = 0.0f;

    stage(0, 0);
    CP_COMMIT();

    for (int ch = 0; ch < NCH; ch++) {
        if (ch + 1 < NCH) {
            stage((ch + 1) * 64, (ch + 1) & 1);
            CP_COMMIT();
            CP_WAIT(1);
        } else {
            CP_WAIT(0);
        }
        __syncthreads();

        const uint32_t* Asw = (const uint32_t*)(dynb + (ch & 1) * BUFB);
        const uint32_t* Bsw = Asw + CM * SAW;
#pragma unroll
        for (int ks = 0; ks < 4; ks++) {             // 4 x k16 = 64
            int k0w = ks * 8;
            uint32_t a[MTT][4];
#pragma unroll
            for (int mt = 0; mt < MTT; mt++) {
                int base = (wm0 + mt * 16 + grp) * SAW + k0w + qid;
                a[mt][0] = Asw[base];
                a[mt][1] = Asw[base + 8 * SAW];
                a[mt][2] = Asw[base + 4];
                a[mt][3] = Asw[base + 8 * SAW + 4];
            }
            uint32_t b[NTT][2];
#pragma unroll
            for (int nt = 0; nt < NTT; nt++) {
                int base = (wn0 + nt * 8 + grp) * SAW + k0w + qid;
                b[nt][0] = Bsw[base];
                b[nt][1] = Bsw[base + 4];
            }
#pragma unroll
            for (int mt = 0; mt < MTT; mt++)
#pragma unroll
                for (int nt = 0; nt < NTT; nt++)
                    mma_bf16(acc[mt][nt][0], acc[mt][nt][1], acc[mt][nt][2], acc[mt][nt][3],
                             a[mt][0], a[mt][1], a[mt][2], a[mt][3],
                             b[nt][0], b[nt][1]);
        }
        __syncthreads();
    }

    // acc -> SMEM out buffer (aliases staging; all cp.async drained)
#pragma unroll
    for (int mt = 0; mt < MTT; mt++) {
        int r = wm0 + mt * 16 + grp;
#pragma unroll
        for (int nt = 0; nt < NTT; nt++) {
            int c = wn0 + nt * 8 + 2 * qid;
            out[r * OST + c]           = acc[mt][nt][0];
            out[r * OST + c + 1]       = acc[mt][nt][1];
            out[(r + 8) * OST + c]     = acc[mt][nt][2];
            out[(r + 8) * OST + c + 1] = acc[mt][nt][3];
        }
    }
    __syncthreads();

    // Apply phase: one (row, d) per item.
    int dgbase = blockIdx.y * DN;
#pragma unroll
    for (int item = tid; item < CM * DN; item += 256) {
        int d   = item & (DN - 1);
        int row = item / DN;
        int R   = row0 + row;
        int dg  = dgbase + d;
        const float* s = out + row * OST + d * GATES;
        if (LEAF) {
            int node = (R >> 9) * NPTn + (R & 511);
            float gi = s[0] + b_iou[dg];
            float go = s[1] + b_iou[128 + dg];
            float gu = s[2] + b_iou[256 + dg];
            float cc = sigm(gi) * tanhf(gu);
            float hh = sigm(go) * tanhf(cc);
            g_c[node * Hn + dg]  = cc;
            g_hb[node * Hn + dg] = __float2bfloat16(hh);
        } else {
            int t = R >> shift, j = R & ((1 << shift) - 1);
            int tb = t * NPTn;
            int node = tb + off + j;
            int left = tb + choff + 2 * j;
            float fl = sigm(s[0] + Ufb[dg]);
            float fr = sigm(s[1] + Ufb[128 + dg]);
            float cred = fl * g_c[left * Hn + dg] + fr * g_c[(left + 1) * Hn + dg];
            float gi = s[2] + b_iou[dg];
            float go = s[3] + b_iou[128 + dg];
            float gu = s[4] + b_iou[256 + dg];
            float cc = sigm(gi) * tanhf(gu) + cred;
            float hh = sigm(go) * tanhf(cc);
            g_c[node * Hn + dg]  = cc;
            g_hb[node * Hn + dg] = __float2bfloat16(hh);
            if (shift == 0)                     // roots: fp32 h for final proj
                g_h[node * Hn + dg] = hh;
        }
    }
}

// Root projection + log_softmax. grid 128 (trees), block 128 (out dims).
__global__ __launch_bounds__(128) void final_kernel(const float* __restrict__ W,
                                                    const float* __restrict__ b,
                                                    float* __restrict__ out) {
    __shared__ float hr[128];
    __shared__ float red[128];
    int t = blockIdx.x, o = threadIdx.x;
    hr[o] = g_h[(t * NPTn + NPTn - 1) * Hn + o];
    __syncthreads();
    float acc = b[o];
#pragma unroll 8
    for (int k = 0; k < 128; k++) acc += hr[k] * W[k * 128 + o];
    red[o] = acc;
    __syncthreads();
#pragma unroll
    for (int s = 64; s > 0; s >>= 1) {
        if (o < s) red[o] = fmaxf(red[o], red[o + s]);
        __syncthreads();
    }
    float mx = red[0];
    __syncthreads();
    red[o] = expf(acc - mx);
    __syncthreads();
#pragma unroll
    for (int s = 64; s > 0; s >>= 1) {
        if (o < s) red[o] += red[o + s];
        __syncthreads();
    }
    out[t * 128 + o] = acc - mx - logf(red[0]);
}

// ---------------------------------------------------------------------------
// Inputs (metadata order): label, emb, W_iou, U_iou, b_iou, U_f_w, U_f_b, W_out, b_out
// ---------------------------------------------------------------------------
// Dynamic smem (bytes): max(out, 2 stage buffers)
#define LEAF_SMEM  ((2 * (128 + 96) * SABY) > (128 * 96 * 4) ? (2 * (128 + 96) * SABY) : (128 * 96 * 4))   // 64512
#define LV128_SMEM ((2 * (128 + 80) * SABY) > (128 * 80 * 4) ? (2 * (128 + 80) * SABY) : (128 * 80 * 4))   // 59904
#define LV64_SMEM  ((2 * (64 + 80) * SABY) > (64 * 80 * 4) ? (2 * (64 + 80) * SABY) : (64 * 80 * 4))       // 41472

extern "C" void kernel_launch(void* const* d_in, const int* in_sizes, int n_in,
                              void* d_out, int out_size) {
    const int*   label = (const int*)  d_in[0];
    const float* emb   = (const float*)d_in[1];
    const float* W_iou = (const float*)d_in[2];
    const float* U_iou = (const float*)d_in[3];
    const float* b_iou = (const float*)d_in[4];
    const float* U_f_w = (const float*)d_in[5];
    const float* U_f_b = (const float*)d_in[6];
    const float* W_out = (const float*)d_in[7];
    const float* b_out = (const float*)d_in[8];
    float* out = (float*)d_out;

    // Opt-in dynamic smem (> 48 KB). Host-side attribute set; capture-safe (R10/R12).
    cudaFuncSetAttribute((const void*)fused_gemm<128, 96, 128, 3, 96, 2, true>,
                         cudaFuncAttributeMaxDynamicSharedMemorySize, LEAF_SMEM);
    cudaFuncSetAttribute((const void*)fused_gemm<128, 80, 256, 5, 80, 3, false>,
                         cudaFuncAttributeMaxDynamicSharedMemorySize, LV128_SMEM);
    cudaFuncSetAttribute((const void*)fused_gemm<64, 80, 256, 5, 80, 3, false>,
                         cudaFuncAttributeMaxDynamicSharedMemorySize, LV64_SMEM);

    prep_WT<<<640, 256>>>(U_f_w, U_iou);
    prep_WioT<<<192, 256>>>(W_iou);
    prep_emb<<<(VOCABn * Hn / 2) / 256, 256>>>(emb);

    // Leaves: fused [65536,128]@[128,384(permuted)] + cell update
    fused_gemm<128, 96, 128, 3, 96, 2, true>
        <<<dim3(NLEAF / 128, 4), 256, LEAF_SMEM>>>(label, b_iou, nullptr, 0, 0, 0);

    for (int shift = 8; shift >= 0; shift--) {
        int cnt   = 1 << shift;                 // 256 .. 1
        int off   = NPTn - (2 * cnt - 1);
        int choff = NPTn - (4 * cnt - 1);
        int nd    = Bn * cnt;                   // 32768 .. 128
        if (nd >= 8192)
            fused_gemm<128, 80, 256, 5, 80, 3, false>
                <<<dim3(nd / 128, 8), 256, LV128_SMEM>>>(label, b_iou, U_f_b,
                                                         shift, off, choff);
        else
            fused_gemm<64, 80, 256, 5, 80, 3, false>
                <<<dim3(nd / 64, 8), 256, LV64_SMEM>>>(label, b_iou, U_f_b,
                                                       shift, off, choff);
    }

    final_kernel<<<Bn, 128>>>(W_out, b_out, out);
}

// round 14
// speedup vs baseline: 5.5388x; 1.0093x over previous
#include <cuda_runtime.h>
#include <cuda_bf16.h>
#include <cstdint>

// Problem constants
#define Hn    128
#define Ln    512
#define Bn    128
#define VOCABn 32000
#define NPTn  1023                 // 2L-1 nodes per tree
#define NTOT  (Bn * NPTn)          // 130944 nodes
#define NLEAF (Bn * Ln)            // 65536 leaves

// Persistent device state (no allocation allowed)
__device__ float g_h[NTOT * Hn];                       // fp32 h (only roots written; final proj)
__device__ float g_c[NTOT * Hn];                       // fp32 c chain
__device__ __nv_bfloat16 g_hb[NTOT * Hn];              // bf16 h mirror (GEMM operand)
__device__ __nv_bfloat16 g_embB[VOCABn * Hn];          // bf16 emb
__device__ __nv_bfloat16 g_WTb[640 * 256];             // permuted [Ufw|Uiou]^T, bf16, [c][k], c=d*5+g
__device__ __nv_bfloat16 g_WioTb[384 * 128];           // permuted W_iou^T, bf16, [c][k], c=d*3+g

__device__ __forceinline__ float sigm(float x) { return 1.0f / (1.0f + expf(-x)); }

// m16n8k16 bf16 MMA, fp32 accum (legacy HMMA path — valid on plain compute_103)
__device__ __forceinline__ void mma_bf16(float& c0, float& c1, float& c2, float& c3,
                                         uint32_t a0, uint32_t a1, uint32_t a2, uint32_t a3,
                                         uint32_t b0, uint32_t b1) {
    asm volatile(
        "mma.sync.aligned.m16n8k16.row.col.f32.bf16.bf16.f32 "
        "{%0,%1,%2,%3}, {%4,%5,%6,%7}, {%8,%9}, {%0,%1,%2,%3};"
        : "+f"(c0), "+f"(c1), "+f"(c2), "+f"(c3)
        : "r"(a0), "r"(a1), "r"(a2), "r"(a3), "r"(b0), "r"(b1));
}

__device__ __forceinline__ void ldsm4(uint32_t& r0, uint32_t& r1, uint32_t& r2, uint32_t& r3,
                                      uint32_t addr) {
    asm volatile("ldmatrix.sync.aligned.m8n8.x4.shared.b16 {%0,%1,%2,%3}, [%4];"
                 : "=r"(r0), "=r"(r1), "=r"(r2), "=r"(r3) : "r"(addr));
}
__device__ __forceinline__ void ldsm2(uint32_t& r0, uint32_t& r1, uint32_t addr) {
    asm volatile("ldmatrix.sync.aligned.m8n8.x2.shared.b16 {%0,%1}, [%2];"
                 : "=r"(r0), "=r"(r1) : "r"(addr));
}

__device__ __forceinline__ uint32_t smem_u32(const void* p) {
    uint32_t a;
    asm("{ .reg .u64 t; cvta.to.shared.u64 t, %1; cvt.u32.u64 %0, t; }" : "=r"(a) : "l"(p));
    return a;
}
__device__ __forceinline__ void cpa16(uint32_t s, const void* g) {
    asm volatile("cp.async.cg.shared.global [%0], [%1], 16;" :: "r"(s), "l"(g));
}
#define CP_COMMIT() asm volatile("cp.async.commit_group;" ::: "memory")
#define CP_WAIT(N)  asm volatile("cp.async.wait_group %0;" :: "n"(N) : "memory")

// ---------------------------------------------------------------------------
// Prep kernels: weight transpose to gate-interleaved K-major bf16; emb -> bf16.
// Level: c = d*5 + g (g0=Ufw[:,d], g1=Ufw[:,128+d], g2..4=Uiou[:,{0,128,256}+d])
// Leaf:  c = d*3 + g (g=Wiou[:, g*128+d])
// ---------------------------------------------------------------------------
__global__ __launch_bounds__(256) void prep_WT(const float* __restrict__ Ufw,
                                               const float* __restrict__ Uiou) {
    int idx = blockIdx.x * 256 + threadIdx.x;
    if (idx >= 640 * 256) return;
    int c = idx >> 8, k = idx & 255;
    int d = c / 5, g = c % 5;
    float v;
    if (g == 0)      v = Ufw[k * 256 + d];
    else if (g == 1) v = Ufw[k * 256 + 128 + d];
    else             v = Uiou[k * 384 + (g - 2) * 128 + d];
    g_WTb[idx] = __float2bfloat16(v);
}
__global__ __launch_bounds__(256) void prep_WioT(const float* __restrict__ Wiou) {
    int idx = blockIdx.x * 256 + threadIdx.x;
    if (idx >= 384 * 128) return;
    int c = idx >> 7, k = idx & 127;
    int d = c / 3, g = c % 3;
    g_WioTb[idx] = __float2bfloat16(Wiou[k * 384 + g * 128 + d]);
}
__global__ __launch_bounds__(256) void prep_emb(const float* __restrict__ emb) {
    int idx = blockIdx.x * 256 + threadIdx.x;           // VOCABn*Hn/2
    float2 v = *(const float2*)(emb + idx * 2);
    __nv_bfloat162 t = __floats2bfloat162_rn(v.x, v.y);
    *(__nv_bfloat162*)(g_embB + idx * 2) = t;
}

// ---------------------------------------------------------------------------
// Fused bf16-MMA GEMM + LSTM-cell-apply, cp.async double-buffered staging,
// ldmatrix fragment loads.
// CTA tile CM x NCOLS (gate-interleaved cols), K in 64-wide chunks.
// Staged rows: 64 bf16 + pad = 144 B (36 words) -> LDSM phases tile all 32
// banks (row r starts at bank 4r mod 32, 4 banks wide). 8 warps: 4(M) x 2(N).
// After mainloop: acc -> SMEM out (stride OST), apply writes g_c / g_hb
// (and fp32 g_h at the root level only). No scratch gmem.
// LEAF:  A = g_embB[label[node]] (K=128), B = g_WioTb, NCOLS=96 (32 d x 3)
// LEVEL: A = 256 bf16 of g_hb at child base (K=256), B = g_WTb, NCOLS=80 (16 d x 5)
// ---------------------------------------------------------------------------
#define SABY 144          // bytes per staged row

template <int CM, int NCOLS, int KTOT, int GATES, int OST, int MINB, bool LEAF>
__global__ __launch_bounds__(256, MINB)
void fused_gemm(const int* __restrict__ label,
                const float* __restrict__ b_iou, const float* __restrict__ Ufb,
                int shift, int off, int choff) {
    const int MTT  = CM / 64;          // m16 tiles per warp (4 M-warps)
    const int NTT  = NCOLS / 16;       // n8 tiles per warp  (2 N-warps)
    const int DN   = NCOLS / GATES;    // d's per CTA
    const int NCH  = KTOT / 64;        // K chunks
    const int BUFB = (CM + NCOLS) * SABY;   // bytes per stage buffer

    extern __shared__ float dyn[];     // 2 stage buffers; out aliases from 0
    char*  dynb = (char*)dyn;
    float* out  = dyn;                 // CM x OST
    __shared__ int abase[CM];

    const __nv_bfloat16* Ab = LEAF ? g_embB : g_hb;
    const __nv_bfloat16* BT = LEAF ? g_WioTb : g_WTb;

    int tid  = threadIdx.x;
    int wid  = tid >> 5, lane = tid & 31;
    int grp  = lane >> 2, qid = lane & 3;
    int row0 = blockIdx.x * CM;
    int col0 = blockIdx.y * NCOLS;
    int wm0  = (wid >> 1) * (CM / 4);
    int wn0  = (wid & 1) * (NCOLS / 2);

    if (tid < CM) {
        int r = row0 + tid;
        int base;
        if (LEAF) {
            int g = (r >> 9) * NPTn + (r & 511);
            base = label[g] * Hn;
        } else {
            int t = r >> shift, j = r & ((1 << shift) - 1);
            base = (t * NPTn + choff + 2 * j) * Hn;
        }
        abase[tid] = base;
    }
    __syncthreads();

    uint32_t sbase = smem_u32(dynb);

    // Per-thread ldmatrix base addresses (buffer 0, chunk 0).
    // A x4 (16x16): phases = rows 0-7 @k0 | rows 8-15 @k0 | rows 0-7 @k8 | rows 8-15 @k8
    int arow = (lane & 7) + ((lane >> 3) & 1) * 8;
    uint32_t aaddr0 = sbase + (uint32_t)(wm0 + arow) * SABY + ((lane >> 4) * 16);
    // B x4 (two n8 tiles): rows n0..7 @k0 | n0..7 @k8 | n8..15 @k0 | n8..15 @k8
    int brow = (lane & 7) + (lane >> 4) * 8;
    uint32_t baddr0 = sbase + (uint32_t)CM * SABY + (uint32_t)(wn0 + brow) * SABY
                    + (((lane >> 3) & 1) * 16);
    // B x2 (odd last tile; lanes 0-15 used): rows n0..7 @k0 | n0..7 @k8
    uint32_t baddr2 = sbase + (uint32_t)CM * SABY + (uint32_t)(wn0 + (lane & 7)) * SABY
                    + (((lane >> 3) & 1) * 16);

    // Stage chunk (kk = bf16 offset) into buffer buf via cp.async.
    auto stage = [&](int kk, int buf) {
        uint32_t sb = sbase + buf * BUFB;
#pragma unroll
        for (int e = 0; e < CM / 32; e++) {          // CM*8 16B transfers
            int i = tid + e * 256;
            int m = i >> 3, q = i & 7;
            cpa16(sb + m * SABY + q * 16, Ab + abase[m] + kk + q * 8);
        }
#pragma unroll
        for (int e = 0; e < (NCOLS * 8 + 255) / 256; e++) {
            int i = tid + e * 256;
            if (i < NCOLS * 8) {
                int n = i >> 3, q = i & 7;
                cpa16(sb + CM * SABY + n * SABY + q * 16,
                      BT + (size_t)(col0 + n) * KTOT + kk + q * 8);
            }
        }
    };

    float acc[MTT][NTT][4];
#pragma unroll
    for (int mt = 0; mt < MTT; mt++)
#pragma unroll
        for (int nt = 0; nt < NTT; nt++)
#pragma unroll
            for (int p = 0; p < 4; p++) acc[mt][nt][p] = 0.0f;

    stage(0, 0);
    CP_COMMIT();

    for (int ch = 0; ch < NCH; ch++) {
        if (ch + 1 < NCH) {
            stage((ch + 1) * 64, (ch + 1) & 1);
            CP_COMMIT();
            CP_WAIT(1);
        } else {
            CP_WAIT(0);
        }
        __syncthreads();

        uint32_t bufo = (uint32_t)(ch & 1) * BUFB;
#pragma unroll
        for (int ks = 0; ks < 4; ks++) {             // 4 x k16 = 64
            uint32_t kb = bufo + ks * 32;            // 16 bf16 = 32 B per ks
            uint32_t a[MTT][4];
#pragma unroll
            for (int mt = 0; mt < MTT; mt++)
                ldsm4(a[mt][0], a[mt][1], a[mt][2], a[mt][3],
                      aaddr0 + kb + mt * 16 * SABY);
            uint32_t b[NTT][2];
#pragma unroll
            for (int np = 0; np < NTT / 2; np++)
                ldsm4(b[2 * np][0], b[2 * np][1], b[2 * np + 1][0], b[2 * np + 1][1],
                      baddr0 + kb + np * 16 * SABY);
            if (NTT & 1)
                ldsm2(b[NTT - 1][0], b[NTT - 1][1],
                      baddr2 + kb + (NTT - 1) * 8 * SABY);
#pragma unroll
            for (int mt = 0; mt < MTT; mt++)
#pragma unroll
                for (int nt = 0; nt < NTT; nt++)
                    mma_bf16(acc[mt][nt][0], acc[mt][nt][1], acc[mt][nt][2], acc[mt][nt][3],
                             a[mt][0], a[mt][1], a[mt][2], a[mt][3],
                             b[nt][0], b[nt][1]);
        }
        __syncthreads();
    }

    // acc -> SMEM out buffer (aliases staging; all cp.async drained)
#pragma unroll
    for (int mt = 0; mt < MTT; mt++) {
        int r = wm0 + mt * 16 + grp;
#pragma unroll
        for (int nt = 0; nt < NTT; nt++) {
            int c = wn0 + nt * 8 + 2 * qid;
            out[r * OST + c]           = acc[mt][nt][0];
            out[r * OST + c + 1]       = acc[mt][nt][1];
            out[(r + 8) * OST + c]     = acc[mt][nt][2];
            out[(r + 8) * OST + c + 1] = acc[mt][nt][3];
        }
    }
    __syncthreads();

    // Apply phase: one (row, d) per item.
    int dgbase = blockIdx.y * DN;
#pragma unroll
    for (int item = tid; item < CM * DN; item += 256) {
        int d   = item & (DN - 1);
        int row = item / DN;
        int R   = row0 + row;
        int dg  = dgbase + d;
        const float* s = out + row * OST + d * GATES;
        if (LEAF) {
            int node = (R >> 9) * NPTn + (R & 511);
            float gi = s[0] + b_iou[dg];
            float go = s[1] + b_iou[128 + dg];
            float gu = s[2] + b_iou[256 + dg];
            float cc = sigm(gi) * tanhf(gu);
            float hh = sigm(go) * tanhf(cc);
            g_c[node * Hn + dg]  = cc;
            g_hb[node * Hn + dg] = __float2bfloat16(hh);
        } else {
            int t = R >> shift, j = R & ((1 << shift) - 1);
            int tb = t * NPTn;
            int node = tb + off + j;
            int left = tb + choff + 2 * j;
            float fl = sigm(s[0] + Ufb[dg]);
            float fr = sigm(s[1] + Ufb[128 + dg]);
            float cred = fl * g_c[left * Hn + dg] + fr * g_c[(left + 1) * Hn + dg];
            float gi = s[2] + b_iou[dg];
            float go = s[3] + b_iou[128 + dg];
            float gu = s[4] + b_iou[256 + dg];
            float cc = sigm(gi) * tanhf(gu) + cred;
            float hh = sigm(go) * tanhf(cc);
            g_c[node * Hn + dg]  = cc;
            g_hb[node * Hn + dg] = __float2bfloat16(hh);
            if (shift == 0)                     // roots: fp32 h for final proj
                g_h[node * Hn + dg] = hh;
        }
    }
}

// Root projection + log_softmax. grid 128 (trees), block 128 (out dims).
__global__ __launch_bounds__(128) void final_kernel(const float* __restrict__ W,
                                                    const float* __restrict__ b,
                                                    float* __restrict__ out) {
    __shared__ float hr[128];
    __shared__ float red[128];
    int t = blockIdx.x, o = threadIdx.x;
    hr[o] = g_h[(t * NPTn + NPTn - 1) * Hn + o];
    __syncthreads();
    float acc = b[o];
#pragma unroll 8
    for (int k = 0; k < 128; k++) acc += hr[k] * W[k * 128 + o];
    red[o] = acc;
    __syncthreads();
#pragma unroll
    for (int s = 64; s > 0; s >>= 1) {
        if (o < s) red[o] = fmaxf(red[o], red[o + s]);
        __syncthreads();
    }
    float mx = red[0];
    __syncthreads();
    red[o] = expf(acc - mx);
    __syncthreads();
#pragma unroll
    for (int s = 64; s > 0; s >>= 1) {
        if (o < s) red[o] += red[o + s];
        __syncthreads();
    }
    out[t * 128 + o] = acc - mx - logf(red[0]);
}

// ---------------------------------------------------------------------------
// Inputs (metadata order): label, emb, W_iou, U_iou, b_iou, U_f_w, U_f_b, W_out, b_out
// ---------------------------------------------------------------------------
// Dynamic smem (bytes): max(out, 2 stage buffers)
#define LEAF_SMEM  ((2 * (128 + 96) * SABY) > (128 * 96 * 4) ? (2 * (128 + 96) * SABY) : (128 * 96 * 4))   // 64512
#define LV128_SMEM ((2 * (128 + 80) * SABY) > (128 * 80 * 4) ? (2 * (128 + 80) * SABY) : (128 * 80 * 4))   // 59904
#define LV64_SMEM  ((2 * (64 + 80) * SABY) > (64 * 80 * 4) ? (2 * (64 + 80) * SABY) : (64 * 80 * 4))       // 41472

extern "C" void kernel_launch(void* const* d_in, const int* in_sizes, int n_in,
                              void* d_out, int out_size) {
    const int*   label = (const int*)  d_in[0];
    const float* emb   = (const float*)d_in[1];
    const float* W_iou = (const float*)d_in[2];
    const float* U_iou = (const float*)d_in[3];
    const float* b_iou = (const float*)d_in[4];
    const float* U_f_w = (const float*)d_in[5];
    const float* U_f_b = (const float*)d_in[6];
    const float* W_out = (const float*)d_in[7];
    const float* b_out = (const float*)d_in[8];
    float* out = (float*)d_out;

    // Opt-in dynamic smem (> 48 KB). Host-side attribute set; capture-safe (R10/R12/R13).
    cudaFuncSetAttribute((const void*)fused_gemm<128, 96, 128, 3, 96, 2, true>,
                         cudaFuncAttributeMaxDynamicSharedMemorySize, LEAF_SMEM);
    cudaFuncSetAttribute((const void*)fused_gemm<128, 80, 256, 5, 80, 3, false>,
                         cudaFuncAttributeMaxDynamicSharedMemorySize, LV128_SMEM);
    cudaFuncSetAttribute((const void*)fused_gemm<64, 80, 256, 5, 80, 3, false>,
                         cudaFuncAttributeMaxDynamicSharedMemorySize, LV64_SMEM);

    prep_WT<<<640, 256>>>(U_f_w, U_iou);
    prep_WioT<<<192, 256>>>(W_iou);
    prep_emb<<<(VOCABn * Hn / 2) / 256, 256>>>(emb);

    // Leaves: fused [65536,128]@[128,384(permuted)] + cell update
    fused_gemm<128, 96, 128, 3, 96, 2, true>
        <<<dim3(NLEAF / 128, 4), 256, LEAF_SMEM>>>(label, b_iou, nullptr, 0, 0, 0);

    for (int shift = 8; shift >= 0; shift--) {
        int cnt   = 1 << shift;                 // 256 .. 1
        int off   = NPTn - (2 * cnt - 1);
        int choff = NPTn - (4 * cnt - 1);
        int nd    = Bn * cnt;                   // 32768 .. 128
        if (nd >= 8192)
            fused_gemm<128, 80, 256, 5, 80, 3, false>
                <<<dim3(nd / 128, 8), 256, LV128_SMEM>>>(label, b_iou, U_f_b,
                                                         shift, off, choff);
        else
            fused_gemm<64, 80, 256, 5, 80, 3, false>
                <<<dim3(nd / 64, 8), 256, LV64_SMEM>>>(label, b_iou, U_f_b,
                                                       shift, off, choff);
    }

    final_kernel<<<Bn, 128>>>(W_out, b_out, out);
}

// round 15
// speedup vs baseline: 6.9820x; 1.2606x over previous
#include <cuda_runtime.h>
#include <cuda_bf16.h>
#include <cstdint>

// Problem constants
#define Hn    128
#define Ln    512
#define Bn    128
#define VOCABn 32000
#define NPTn  1023                 // 2L-1 nodes per tree
#define NTOT  (Bn * NPTn)          // 130944 nodes
#define NLEAF (Bn * Ln)            // 65536 leaves

// Persistent device state (no allocation allowed)
__device__ float g_h[NTOT * Hn];                       // fp32 h (only roots written; final proj)
__device__ float g_c[NTOT * Hn];                       // fp32 c chain
__device__ __nv_bfloat16 g_hb[NTOT * Hn];              // bf16 h mirror (GEMM operand)
__device__ __nv_bfloat16 g_embB[VOCABn * Hn];          // bf16 emb
__device__ __nv_bfloat16 g_WTb[640 * 256];             // permuted [Ufw|Uiou]^T, bf16, [c][k], c=d*5+g
__device__ __nv_bfloat16 g_WioTb[384 * 128];           // permuted W_iou^T, bf16, [c][k], c=d*3+g

// HW tanh (single MUFU op, sm_75+); sigmoid via tanh identity.
__device__ __forceinline__ float tanh_ap(float x) {
    float r; asm("tanh.approx.f32 %0, %1;" : "=f"(r) : "f"(x)); return r;
}
__device__ __forceinline__ float sigm_ap(float x) {
    return fmaf(0.5f, tanh_ap(0.5f * x), 0.5f);
}

// m16n8k16 bf16 MMA, fp32 accum (legacy HMMA path — valid on plain compute_103)
__device__ __forceinline__ void mma_bf16(float& c0, float& c1, float& c2, float& c3,
                                         uint32_t a0, uint32_t a1, uint32_t a2, uint32_t a3,
                                         uint32_t b0, uint32_t b1) {
    asm volatile(
        "mma.sync.aligned.m16n8k16.row.col.f32.bf16.bf16.f32 "
        "{%0,%1,%2,%3}, {%4,%5,%6,%7}, {%8,%9}, {%0,%1,%2,%3};"
        : "+f"(c0), "+f"(c1), "+f"(c2), "+f"(c3)
        : "r"(a0), "r"(a1), "r"(a2), "r"(a3), "r"(b0), "r"(b1));
}

__device__ __forceinline__ void ldsm4(uint32_t& r0, uint32_t& r1, uint32_t& r2, uint32_t& r3,
                                      uint32_t addr) {
    asm volatile("ldmatrix.sync.aligned.m8n8.x4.shared.b16 {%0,%1,%2,%3}, [%4];"
                 : "=r"(r0), "=r"(r1), "=r"(r2), "=r"(r3) : "r"(addr));
}
__device__ __forceinline__ void ldsm2(uint32_t& r0, uint32_t& r1, uint32_t addr) {
    asm volatile("ldmatrix.sync.aligned.m8n8.x2.shared.b16 {%0,%1}, [%2];"
                 : "=r"(r0), "=r"(r1) : "r"(addr));
}

__device__ __forceinline__ uint32_t smem_u32(const void* p) {
    uint32_t a;
    asm("{ .reg .u64 t; cvta.to.shared.u64 t, %1; cvt.u32.u64 %0, t; }" : "=r"(a) : "l"(p));
    return a;
}
__device__ __forceinline__ void cpa16(uint32_t s, const void* g) {
    asm volatile("cp.async.cg.shared.global [%0], [%1], 16;" :: "r"(s), "l"(g));
}
#define CP_COMMIT() asm volatile("cp.async.commit_group;" ::: "memory")
#define CP_WAIT(N)  asm volatile("cp.async.wait_group %0;" :: "n"(N) : "memory")

// ---------------------------------------------------------------------------
// Prep kernels: weight transpose to gate-interleaved K-major bf16; emb -> bf16.
// ---------------------------------------------------------------------------
__global__ __launch_bounds__(256) void prep_WT(const float* __restrict__ Ufw,
                                               const float* __restrict__ Uiou) {
    int idx = blockIdx.x * 256 + threadIdx.x;
    if (idx >= 640 * 256) return;
    int c = idx >> 8, k = idx & 255;
    int d = c / 5, g = c % 5;
    float v;
    if (g == 0)      v = Ufw[k * 256 + d];
    else if (g == 1) v = Ufw[k * 256 + 128 + d];
    else             v = Uiou[k * 384 + (g - 2) * 128 + d];
    g_WTb[idx] = __float2bfloat16(v);
}
__global__ __launch_bounds__(256) void prep_WioT(const float* __restrict__ Wiou) {
    int idx = blockIdx.x * 256 + threadIdx.x;
    if (idx >= 384 * 128) return;
    int c = idx >> 7, k = idx & 127;
    int d = c / 3, g = c % 3;
    g_WioTb[idx] = __float2bfloat16(Wiou[k * 384 + g * 128 + d]);
}
__global__ __launch_bounds__(256) void prep_emb(const float* __restrict__ emb) {
    int idx = blockIdx.x * 256 + threadIdx.x;           // VOCABn*Hn/2
    float2 v = *(const float2*)(emb + idx * 2);
    __nv_bfloat162 t = __floats2bfloat162_rn(v.x, v.y);
    *(__nv_bfloat162*)(g_embB + idx * 2) = t;
}

// ---------------------------------------------------------------------------
// Fused bf16-MMA GEMM + LSTM-cell-apply, cp.async double-buffered staging,
// ldmatrix fragment loads, conflict-tuned OST, hw-tanh gates.
// LEAF:  A = g_embB[label[node]] (K=128), B = g_WioTb, NCOLS=96 (32 d x 3), OST=101
// LEVEL: A = 256 bf16 of g_hb at child base (K=256), B = g_WTb, NCOLS=80 (16 d x 5), OST=85
// ---------------------------------------------------------------------------
#define SABY 144          // bytes per staged row

template <int CM, int NCOLS, int KTOT, int GATES, int OST, int MINB, bool LEAF>
__global__ __launch_bounds__(256, MINB)
void fused_gemm(const int* __restrict__ label,
                const float* __restrict__ b_iou, const float* __restrict__ Ufb,
                int shift, int off, int choff) {
    const int MTT  = CM / 64;          // m16 tiles per warp (4 M-warps)
    const int NTT  = NCOLS / 16;       // n8 tiles per warp  (2 N-warps)
    const int DN   = NCOLS / GATES;    // d's per CTA (power of 2: 32 leaf, 16 level)
    const int LOGD = (DN == 32) ? 5 : 4;
    const int NCH  = KTOT / 64;        // K chunks
    const int BUFB = (CM + NCOLS) * SABY;   // bytes per stage buffer

    extern __shared__ float dyn[];     // 2 stage buffers; out aliases from 0
    char*  dynb = (char*)dyn;
    float* out  = dyn;                 // CM x OST
    __shared__ int abase[CM];

    const __nv_bfloat16* Ab = LEAF ? g_embB : g_hb;
    const __nv_bfloat16* BT = LEAF ? g_WioTb : g_WTb;

    int tid  = threadIdx.x;
    int wid  = tid >> 5, lane = tid & 31;
    int grp  = lane >> 2, qid = lane & 3;
    int row0 = blockIdx.x * CM;
    int col0 = blockIdx.y * NCOLS;
    int wm0  = (wid >> 1) * (CM / 4);
    int wn0  = (wid & 1) * (NCOLS / 2);

    if (tid < CM) {
        int r = row0 + tid;
        int base;
        if (LEAF) {
            int g = (r >> 9) * NPTn + (r & 511);
            base = label[g] * Hn;
        } else {
            int t = r >> shift, j = r & ((1 << shift) - 1);
            base = (t * NPTn + choff + 2 * j) * Hn;
        }
        abase[tid] = base;
    }
    __syncthreads();

    uint32_t sbase = smem_u32(dynb);

    // Per-thread ldmatrix base addresses (buffer 0, chunk 0).
    int arow = (lane & 7) + ((lane >> 3) & 1) * 8;
    uint32_t aaddr0 = sbase + (uint32_t)(wm0 + arow) * SABY + ((lane >> 4) * 16);
    int brow = (lane & 7) + (lane >> 4) * 8;
    uint32_t baddr0 = sbase + (uint32_t)CM * SABY + (uint32_t)(wn0 + brow) * SABY
                    + (((lane >> 3) & 1) * 16);
    uint32_t baddr2 = sbase + (uint32_t)CM * SABY + (uint32_t)(wn0 + (lane & 7)) * SABY
                    + (((lane >> 3) & 1) * 16);

    auto stage = [&](int kk, int buf) {
        uint32_t sb = sbase + buf * BUFB;
#pragma unroll
        for (int e = 0; e < CM / 32; e++) {
            int i = tid + e * 256;
            int m = i >> 3, q = i & 7;
            cpa16(sb + m * SABY + q * 16, Ab + abase[m] + kk + q * 8);
        }
#pragma unroll
        for (int e = 0; e < (NCOLS * 8 + 255) / 256; e++) {
            int i = tid + e * 256;
            if (i < NCOLS * 8) {
                int n = i >> 3, q = i & 7;
                cpa16(sb + CM * SABY + n * SABY + q * 16,
                      BT + (size_t)(col0 + n) * KTOT + kk + q * 8);
            }
        }
    };

    float acc[MTT][NTT][4];
#pragma unroll
    for (int mt = 0; mt < MTT; mt++)
#pragma unroll
        for (int nt = 0; nt < NTT; nt++)
#pragma unroll
            for (int p = 0; p < 4; p++) acc[mt][nt][p] = 0.0f;

    stage(0, 0);
    CP_COMMIT();

    for (int ch = 0; ch < NCH; ch++) {
        if (ch + 1 < NCH) {
            stage((ch + 1) * 64, (ch + 1) & 1);
            CP_COMMIT();
            CP_WAIT(1);
        } else {
            CP_WAIT(0);
        }
        __syncthreads();

        uint32_t bufo = (uint32_t)(ch & 1) * BUFB;
#pragma unroll
        for (int ks = 0; ks < 4; ks++) {             // 4 x k16 = 64
            uint32_t kb = bufo + ks * 32;            // 16 bf16 = 32 B per ks
            uint32_t a[MTT][4];
#pragma unroll
            for (int mt = 0; mt < MTT; mt++)
                ldsm4(a[mt][0], a[mt][1], a[mt][2], a[mt][3],
                      aaddr0 + kb + mt * 16 * SABY);
            uint32_t b[NTT][2];
#pragma unroll
            for (int np = 0; np < NTT / 2; np++)
                ldsm4(b[2 * np][0], b[2 * np][1], b[2 * np + 1][0], b[2 * np + 1][1],
                      baddr0 + kb + np * 16 * SABY);
            if (NTT & 1)
                ldsm2(b[NTT - 1][0], b[NTT - 1][1],
                      baddr2 + kb + (NTT - 1) * 8 * SABY);
#pragma unroll
            for (int mt = 0; mt < MTT; mt++)
#pragma unroll
                for (int nt = 0; nt < NTT; nt++)
                    mma_bf16(acc[mt][nt][0], acc[mt][nt][1], acc[mt][nt][2], acc[mt][nt][3],
                             a[mt][0], a[mt][1], a[mt][2], a[mt][3],
                             b[nt][0], b[nt][1]);
        }
        __syncthreads();
    }

    // acc -> SMEM out buffer (odd OST: stores at most 2-way conflicted)
#pragma unroll
    for (int mt = 0; mt < MTT; mt++) {
        int r = wm0 + mt * 16 + grp;
#pragma unroll
        for (int nt = 0; nt < NTT; nt++) {
            int c = wn0 + nt * 8 + 2 * qid;
            out[r * OST + c]           = acc[mt][nt][0];
            out[r * OST + c + 1]       = acc[mt][nt][1];
            out[(r + 8) * OST + c]     = acc[mt][nt][2];
            out[(r + 8) * OST + c + 1] = acc[mt][nt][3];
        }
    }
    __syncthreads();

    // Apply phase: d is invariant per thread (256 % DN == 0) -> hoist biases.
    int d      = tid & (DN - 1);
    int rbase  = tid >> LOGD;
    const int rstep = 256 >> LOGD;
    int dg = blockIdx.y * DN + d;

    float bi = b_iou[dg], bo = b_iou[128 + dg], bu = b_iou[256 + dg];
    float bfl = 0.0f, bfr = 0.0f;
    if (!LEAF) { bfl = Ufb[dg]; bfr = Ufb[128 + dg]; }

#pragma unroll 4
    for (int row = rbase; row < CM; row += rstep) {
        int R = row0 + row;
        const float* s = out + row * OST + d * GATES;
        if (LEAF) {
            int node = (R >> 9) * NPTn + (R & 511);
            float cc = sigm_ap(s[0] + bi) * tanh_ap(s[2] + bu);
            float hh = sigm_ap(s[1] + bo) * tanh_ap(cc);
            g_c[node * Hn + dg]  = cc;
            g_hb[node * Hn + dg] = __float2bfloat16(hh);
        } else {
            int t = R >> shift, j = R & ((1 << shift) - 1);
            int tb = t * NPTn;
            int node = tb + off + j;
            int left = tb + choff + 2 * j;
            float fl = sigm_ap(s[0] + bfl);
            float fr = sigm_ap(s[1] + bfr);
            float cred = fl * g_c[left * Hn + dg] + fr * g_c[(left + 1) * Hn + dg];
            float cc = sigm_ap(s[2] + bi) * tanh_ap(s[4] + bu) + cred;
            float hh = sigm_ap(s[3] + bo) * tanh_ap(cc);
            g_c[node * Hn + dg]  = cc;
            g_hb[node * Hn + dg] = __float2bfloat16(hh);
            if (shift == 0)                     // roots: fp32 h for final proj
                g_h[node * Hn + dg] = hh;
        }
    }
}

// Root projection + log_softmax. grid 128 (trees), block 128 (out dims).
__global__ __launch_bounds__(128) void final_kernel(const float* __restrict__ W,
                                                    const float* __restrict__ b,
                                                    float* __restrict__ out) {
    __shared__ float hr[128];
    __shared__ float red[128];
    int t = blockIdx.x, o = threadIdx.x;
    hr[o] = g_h[(t * NPTn + NPTn - 1) * Hn + o];
    __syncthreads();
    float acc = b[o];
#pragma unroll 8
    for (int k = 0; k < 128; k++) acc += hr[k] * W[k * 128 + o];
    red[o] = acc;
    __syncthreads();
#pragma unroll
    for (int s = 64; s > 0; s >>= 1) {
        if (o < s) red[o] = fmaxf(red[o], red[o + s]);
        __syncthreads();
    }
    float mx = red[0];
    __syncthreads();
    red[o] = expf(acc - mx);
    __syncthreads();
#pragma unroll
    for (int s = 64; s > 0; s >>= 1) {
        if (o < s) red[o] += red[o + s];
        __syncthreads();
    }
    out[t * 128 + o] = acc - mx - logf(red[0]);
}

// ---------------------------------------------------------------------------
// Inputs (metadata order): label, emb, W_iou, U_iou, b_iou, U_f_w, U_f_b, W_out, b_out
// ---------------------------------------------------------------------------
// Dynamic smem (bytes): max(out, 2 stage buffers)
#define LEAF_SMEM  ((2 * (128 + 96) * SABY) > (128 * 101 * 4) ? (2 * (128 + 96) * SABY) : (128 * 101 * 4))  // 64512
#define LV128_SMEM ((2 * (128 + 80) * SABY) > (128 * 85 * 4) ? (2 * (128 + 80) * SABY) : (128 * 85 * 4))    // 59904
#define LV64_SMEM  ((2 * (64 + 80) * SABY) > (64 * 85 * 4) ? (2 * (64 + 80) * SABY) : (64 * 85 * 4))        // 41472

extern "C" void kernel_launch(void* const* d_in, const int* in_sizes, int n_in,
                              void* d_out, int out_size) {
    const int*   label = (const int*)  d_in[0];
    const float* emb   = (const float*)d_in[1];
    const float* W_iou = (const float*)d_in[2];
    const float* U_iou = (const float*)d_in[3];
    const float* b_iou = (const float*)d_in[4];
    const float* U_f_w = (const float*)d_in[5];
    const float* U_f_b = (const float*)d_in[6];
    const float* W_out = (const float*)d_in[7];
    const float* b_out = (const float*)d_in[8];
    float* out = (float*)d_out;

    // Opt-in dynamic smem (> 48 KB). Host-side attribute set; capture-safe (R10/R12/R13).
    cudaFuncSetAttribute((const void*)fused_gemm<128, 96, 128, 3, 101, 2, true>,
                         cudaFuncAttributeMaxDynamicSharedMemorySize, LEAF_SMEM);
    cudaFuncSetAttribute((const void*)fused_gemm<128, 80, 256, 5, 85, 3, false>,
                         cudaFuncAttributeMaxDynamicSharedMemorySize, LV128_SMEM);
    cudaFuncSetAttribute((const void*)fused_gemm<64, 80, 256, 5, 85, 3, false>,
                         cudaFuncAttributeMaxDynamicSharedMemorySize, LV64_SMEM);

    prep_WT<<<640, 256>>>(U_f_w, U_iou);
    prep_WioT<<<192, 256>>>(W_iou);
    prep_emb<<<(VOCABn * Hn / 2) / 256, 256>>>(emb);

    // Leaves: fused [65536,128]@[128,384(permuted)] + cell update
    fused_gemm<128, 96, 128, 3, 101, 2, true>
        <<<dim3(NLEAF / 128, 4), 256, LEAF_SMEM>>>(label, b_iou, nullptr, 0, 0, 0);

    for (int shift = 8; shift >= 0; shift--) {
        int cnt   = 1 << shift;                 // 256 .. 1
        int off   = NPTn - (2 * cnt - 1);
        int choff = NPTn - (4 * cnt - 1);
        int nd    = Bn * cnt;                   // 32768 .. 128
        if (nd >= 8192)
            fused_gemm<128, 80, 256, 5, 85, 3, false>
                <<<dim3(nd / 128, 8), 256, LV128_SMEM>>>(label, b_iou, U_f_b,
                                                         shift, off, choff);
        else
            fused_gemm<64, 80, 256, 5, 85, 3, false>
                <<<dim3(nd / 64, 8), 256, LV64_SMEM>>>(label, b_iou, U_f_b,
                                                       shift, off, choff);
    }

    final_kernel<<<Bn, 128>>>(W_out, b_out, out);
}